// round 5
// baseline (speedup 1.0000x reference)
#include <cuda_runtime.h>
#include <cuda_bf16.h>
#include <cstdint>

#define B_  64
#define T_  4096
#define E_  512
#define A_  256

// ---------------------------------------------------------------------------
// scratch (allocation-free)
// ---------------------------------------------------------------------------
__device__ float g_dproj[B_ * A_];
__device__ float g_cpart[8 * B_ * E_];
__device__ __align__(128) __nv_bfloat16 g_Wh[A_ * E_];   // [n][k] K-major
__device__ __align__(128) __nv_bfloat16 g_Wl[A_ * E_];

// ---------------------------------------------------------------------------
// helpers
// ---------------------------------------------------------------------------
__device__ __forceinline__ uint32_t smem_u32(const void* p) {
    uint32_t a;
    asm("{ .reg .u64 t; cvta.to.shared.u64 t, %1; cvt.u32.u64 %0, t; }" : "=r"(a) : "l"(p));
    return a;
}
__device__ __forceinline__ uint32_t swz64(uint32_t o) { return o ^ ((o >> 3) & 0x30); }

#define CP_ASYNC16(dst, src) \
    asm volatile("cp.async.cg.shared.global [%0], [%1], 16;" :: "r"(dst), "l"(src) : "memory")
#define CP_COMMIT()  asm volatile("cp.async.commit_group;" ::: "memory")
#define CP_WAIT1()   asm volatile("cp.async.wait_group 1;" ::: "memory")
#define CP_WAIT0()   asm volatile("cp.async.wait_group 0;" ::: "memory")

#define LDM4(r, a) \
    asm volatile("ldmatrix.sync.aligned.m8n8.x4.shared.b16 {%0,%1,%2,%3}, [%4];" \
        : "=r"((r)[0]), "=r"((r)[1]), "=r"((r)[2]), "=r"((r)[3]) : "r"(a))

__device__ __forceinline__ void mma_bf16(float* c, const uint32_t* a, const uint32_t* b) {
    asm volatile(
        "mma.sync.aligned.m16n8k16.row.col.f32.bf16.bf16.f32 "
        "{%0,%1,%2,%3}, {%4,%5,%6,%7}, {%8,%9}, {%0,%1,%2,%3};"
        : "+f"(c[0]), "+f"(c[1]), "+f"(c[2]), "+f"(c[3])
        : "r"(a[0]), "r"(a[1]), "r"(a[2]), "r"(a[3]), "r"(b[0]), "r"(b[1]));
}

// ---------------------------------------------------------------------------
// small prep kernels
// ---------------------------------------------------------------------------
__global__ void convert_w_kernel(const float* __restrict__ W) {
    int k = blockIdx.x;     // 512
    int n = threadIdx.x;    // 256
    float w = W[k * A_ + n];
    __nv_bfloat16 h = __float2bfloat16_rn(w);
    g_Wh[n * E_ + k] = h;
    g_Wl[n * E_ + k] = __float2bfloat16_rn(w - __bfloat162float(h));
}

__global__ void dproj_kernel(const float* __restrict__ dec,
                             const float* __restrict__ Wd,
                             const float* __restrict__ b_enc) {
    int b = blockIdx.x;
    int a = threadIdx.x;
    const float* d = dec + b * E_;
    float s = b_enc[a];
    #pragma unroll 8
    for (int e = 0; e < E_; ++e)
        s = fmaf(d[e], Wd[e * A_ + a], s);
    g_dproj[b * A_ + a] = s;
}

// ---------------------------------------------------------------------------
// K1: HMMA scores GEMM, fused fp32->bf16(hi,lo) split.
// CTA: M=128 x N=256, K=512 (16 chunks of 32). 16 warps (4M x 4N), warp 32x64.
// 512 threads -> 4 warps/SMSP for latency hiding. acc = 64 regs/thread.
// ---------------------------------------------------------------------------
#define KC       32
#define NCH      16
#define OFF_XF   0                      // 2 x 16KB fp32 stage
#define OFF_XH   32768                  // 8KB
#define OFF_XL   40960                  // 8KB
#define OFF_WH   49152                  // 2 x 16KB
#define OFF_WL   81920                  // 2 x 16KB
#define OFF_V    114688
#define OFF_DP   115712
#define OFF_RED  116736                 // 128 x 4 floats
#define SMEM_TOTAL 118784

__global__ void __launch_bounds__(512, 1)
scores_mma_kernel(const float* __restrict__ X,
                  const float* __restrict__ v_att,
                  const float* __restrict__ b_att,
                  float* __restrict__ scores)
{
    extern __shared__ char smem[];
    const uint32_t sb = smem_u32(smem);
    const int tid = threadIdx.x;
    const int lane = tid & 31, wid = tid >> 5;
    const int wm = wid >> 2, wn = wid & 3;      // 4 x 4 warp grid
    const int b = blockIdx.y;
    const int t0 = blockIdx.x * 128;

    float* vs  = (float*)(smem + OFF_V);
    float* dps = (float*)(smem + OFF_DP);
    float* red = (float*)(smem + OFF_RED);
    if (tid < 256) {
        vs[tid]  = v_att[tid];
        dps[tid] = g_dproj[b * A_ + tid];
    }

    const float* xrow = X + ((size_t)b * T_ + t0) * E_;

    float acc[2][8][4];
    #pragma unroll
    for (int mt = 0; mt < 2; ++mt)
        #pragma unroll
        for (int nt = 0; nt < 8; ++nt)
            #pragma unroll
            for (int e = 0; e < 4; ++e) acc[mt][nt][e] = 0.f;

    // per-lane ldmatrix row offsets (unswizzled, 64B rows)
    const int rsel = lane & 15, chalf = lane >> 4;
    uint32_t arow[2], brow[4];
    #pragma unroll
    for (int mt = 0; mt < 2; ++mt)
        arow[mt] = (uint32_t)(((wm << 5) + (mt << 4) + rsel) << 6) + (chalf << 4);
    #pragma unroll
    for (int n2 = 0; n2 < 4; ++n2)
        brow[n2] = (uint32_t)(((wn << 6) + (n2 << 4) + rsel) << 6) + (chalf << 4);

    const uint32_t xh_b = sb + OFF_XH;
    const uint32_t xl_b = sb + OFF_XL;

    // chunk loader: fp32 X tile (128x32) + W hi/lo tiles (256x32 bf16)
    auto load_chunk = [&](int c) {
        const int kc = c * KC;
        const uint32_t s14 = (uint32_t)(c & 1) << 14;
        #pragma unroll
        for (int it = 0; it < 2; ++it) {           // X: 1024 x 16B
            int i = tid + (it << 9);
            int r = i >> 3, q = i & 7;
            const float* src = xrow + (size_t)r * E_ + kc + (q << 2);
            CP_ASYNC16(sb + OFF_XF + s14 + (uint32_t)(i << 4), src);
        }
        #pragma unroll
        for (int it = 0; it < 4; ++it) {           // W: 2048 x 16B
            int i = tid + (it << 9);
            int sp = i >> 10, r = (i >> 2) & 255, q = i & 3;
            const __nv_bfloat16* src = (sp ? g_Wl : g_Wh) + (size_t)r * E_ + kc + (q << 3);
            uint32_t dst = sb + (sp ? OFF_WL : OFF_WH) + s14 + swz64((r << 6) + (q << 4));
            CP_ASYNC16(dst, src);
        }
        CP_COMMIT();
    };

    load_chunk(0);

    for (int c = 0; c < NCH; ++c) {
        if (c + 1 < NCH) { load_chunk(c + 1); CP_WAIT1(); }
        else             { CP_WAIT0(); }
        __syncthreads();                           // stage c ready; Xh/Xl free

        // convert fp32 stage -> swizzled bf16 Xh/Xl
        {
            const char* xf = smem + OFF_XF + ((c & 1) << 14);
            #pragma unroll
            for (int it = 0; it < 2; ++it) {
                int g = tid + (it << 9);
                int r = g >> 3, q = g & 7;
                float4 v = *(const float4*)(xf + (g << 4));
                __nv_bfloat16 h0 = __float2bfloat16_rn(v.x);
                __nv_bfloat16 h1 = __float2bfloat16_rn(v.y);
                __nv_bfloat16 h2 = __float2bfloat16_rn(v.z);
                __nv_bfloat16 h3 = __float2bfloat16_rn(v.w);
                uint32_t hi0 = (uint32_t)__bfloat16_as_ushort(h0) |
                               ((uint32_t)__bfloat16_as_ushort(h1) << 16);
                uint32_t hi1 = (uint32_t)__bfloat16_as_ushort(h2) |
                               ((uint32_t)__bfloat16_as_ushort(h3) << 16);
                uint32_t lo0 = (uint32_t)__bfloat16_as_ushort(__float2bfloat16_rn(v.x - __bfloat162float(h0))) |
                               ((uint32_t)__bfloat16_as_ushort(__float2bfloat16_rn(v.y - __bfloat162float(h1))) << 16);
                uint32_t lo1 = (uint32_t)__bfloat16_as_ushort(__float2bfloat16_rn(v.z - __bfloat162float(h2))) |
                               ((uint32_t)__bfloat16_as_ushort(__float2bfloat16_rn(v.w - __bfloat162float(h3))) << 16);
                uint32_t off = swz64((uint32_t)((r << 6) + (q << 3)));
                *(uint2*)(smem + OFF_XH + off) = make_uint2(hi0, hi1);
                *(uint2*)(smem + OFF_XL + off) = make_uint2(lo0, lo1);
            }
        }
        __syncthreads();                           // Xh/Xl ready

        const uint32_t wh = sb + OFF_WH + ((uint32_t)(c & 1) << 14);
        const uint32_t wl = sb + OFF_WL + ((uint32_t)(c & 1) << 14);

        #pragma unroll
        for (int ks = 0; ks < 2; ++ks) {
            const uint32_t koff = ks << 5;
            uint32_t Ah[2][4], Al[2][4], Bf[4][4];

            #pragma unroll
            for (int mt = 0; mt < 2; ++mt) {
                LDM4(Ah[mt], xh_b + swz64(arow[mt] + koff));
                LDM4(Al[mt], xl_b + swz64(arow[mt] + koff));
            }
            #pragma unroll
            for (int n2 = 0; n2 < 4; ++n2) LDM4(Bf[n2], wh + swz64(brow[n2] + koff));

            // term 1: Xh * Wh   (16 distinct accs)
            #pragma unroll
            for (int n2 = 0; n2 < 4; ++n2) {
                uint32_t be[2] = { Bf[n2][0], Bf[n2][2] };
                uint32_t bo[2] = { Bf[n2][1], Bf[n2][3] };
                #pragma unroll
                for (int mt = 0; mt < 2; ++mt) {
                    mma_bf16(acc[mt][n2 * 2],     Ah[mt], be);
                    mma_bf16(acc[mt][n2 * 2 + 1], Ah[mt], bo);
                }
            }
            // term 2: Xl * Wh   (reuse Bf, distance 16)
            #pragma unroll
            for (int n2 = 0; n2 < 4; ++n2) {
                uint32_t be[2] = { Bf[n2][0], Bf[n2][2] };
                uint32_t bo[2] = { Bf[n2][1], Bf[n2][3] };
                #pragma unroll
                for (int mt = 0; mt < 2; ++mt) {
                    mma_bf16(acc[mt][n2 * 2],     Al[mt], be);
                    mma_bf16(acc[mt][n2 * 2 + 1], Al[mt], bo);
                }
            }
            // term 3: Xh * Wl
            #pragma unroll
            for (int n2 = 0; n2 < 4; ++n2) LDM4(Bf[n2], wl + swz64(brow[n2] + koff));
            #pragma unroll
            for (int n2 = 0; n2 < 4; ++n2) {
                uint32_t be[2] = { Bf[n2][0], Bf[n2][2] };
                uint32_t bo[2] = { Bf[n2][1], Bf[n2][3] };
                #pragma unroll
                for (int mt = 0; mt < 2; ++mt) {
                    mma_bf16(acc[mt][n2 * 2],     Ah[mt], be);
                    mma_bf16(acc[mt][n2 * 2 + 1], Ah[mt], bo);
                }
            }
        }
        __syncthreads();                           // done reading stage c
    }

    // epilogue: tanh + v dot, reduce within warp quads, then across wn
    const int g = lane >> 2, t = lane & 3;
    #pragma unroll
    for (int mt = 0; mt < 2; ++mt) {
        float pa = 0.f, pb = 0.f;
        #pragma unroll
        for (int nt = 0; nt < 8; ++nt) {
            int col = (wn << 6) + (nt << 3) + (t << 1);
            float v0 = vs[col], v1 = vs[col + 1];
            float d0 = dps[col], d1 = dps[col + 1];
            pa = fmaf(v0, tanhf(acc[mt][nt][0] + d0), pa);
            pa = fmaf(v1, tanhf(acc[mt][nt][1] + d1), pa);
            pb = fmaf(v0, tanhf(acc[mt][nt][2] + d0), pb);
            pb = fmaf(v1, tanhf(acc[mt][nt][3] + d1), pb);
        }
        pa += __shfl_xor_sync(0xffffffffu, pa, 1);
        pa += __shfl_xor_sync(0xffffffffu, pa, 2);
        pb += __shfl_xor_sync(0xffffffffu, pb, 1);
        pb += __shfl_xor_sync(0xffffffffu, pb, 2);
        if (t == 0) {
            int row = (wm << 5) + (mt << 4) + g;
            red[row * 4 + wn]       = pa;
            red[(row + 8) * 4 + wn] = pb;
        }
    }
    __syncthreads();

    if (tid < 128) {
        float s = red[tid * 4] + red[tid * 4 + 1] + red[tid * 4 + 2] + red[tid * 4 + 3];
        scores[(size_t)b * T_ + t0 + tid] = s + b_att[0];
    }
}

// ---------------------------------------------------------------------------
// K2: softmax over T per batch
// ---------------------------------------------------------------------------
__global__ void softmax_kernel(float* __restrict__ w) {
    const int b = blockIdx.x;
    float* row = w + (size_t)b * T_;
    const int tid = threadIdx.x, lane = tid & 31, wd = tid >> 5;
    __shared__ float sm[32];
    __shared__ float s_b;

    float v[4];
    float m = -1e30f;
    #pragma unroll
    for (int i = 0; i < 4; ++i) { v[i] = row[tid + (i << 10)]; m = fmaxf(m, v[i]); }
    #pragma unroll
    for (int o = 16; o; o >>= 1) m = fmaxf(m, __shfl_xor_sync(0xffffffffu, m, o));
    if (lane == 0) sm[wd] = m;
    __syncthreads();
    if (tid < 32) {
        float t = sm[tid];
        #pragma unroll
        for (int o = 16; o; o >>= 1) t = fmaxf(t, __shfl_xor_sync(0xffffffffu, t, o));
        if (tid == 0) s_b = t;
    }
    __syncthreads();
    const float mx = s_b;

    float s = 0.f;
    #pragma unroll
    for (int i = 0; i < 4; ++i) { v[i] = __expf(v[i] - mx); s += v[i]; }
    #pragma unroll
    for (int o = 16; o; o >>= 1) s += __shfl_xor_sync(0xffffffffu, s, o);
    if (lane == 0) sm[wd] = s;
    __syncthreads();
    if (tid < 32) {
        float t = sm[tid];
        #pragma unroll
        for (int o = 16; o; o >>= 1) t += __shfl_xor_sync(0xffffffffu, t, o);
        if (tid == 0) s_b = t;
    }
    __syncthreads();
    const float inv = 1.0f / s_b;
    #pragma unroll
    for (int i = 0; i < 4; ++i) row[tid + (i << 10)] = v[i] * inv;
}

// ---------------------------------------------------------------------------
// K3/K4: context
// ---------------------------------------------------------------------------
__global__ void cpart_kernel(const float* __restrict__ X,
                             const float* __restrict__ w) {
    const int c = blockIdx.x, b = blockIdx.y, e = threadIdx.x;
    const float* xb = X + ((size_t)b * T_ + (size_t)c * 512) * E_ + e;
    const float* wb = w + (size_t)b * T_ + (size_t)c * 512;
    float a[8] = {0,0,0,0,0,0,0,0};
    #pragma unroll 2
    for (int t = 0; t < 512; t += 8) {
        #pragma unroll
        for (int u = 0; u < 8; ++u)
            a[u] = fmaf(wb[t + u], xb[(size_t)(t + u) * E_], a[u]);
    }
    g_cpart[((size_t)c * B_ + b) * E_ + e] =
        ((a[0] + a[1]) + (a[2] + a[3])) + ((a[4] + a[5]) + (a[6] + a[7]));
}

__global__ void creduce_kernel(float* __restrict__ ctx) {
    int i = blockIdx.x * blockDim.x + threadIdx.x;
    int b = i >> 9, e = i & 511;
    float s = 0.f;
    #pragma unroll
    for (int c = 0; c < 8; ++c)
        s += g_cpart[((size_t)c * B_ + b) * E_ + e];
    ctx[i] = s;
}

// ---------------------------------------------------------------------------
extern "C" void kernel_launch(void* const* d_in, const int* in_sizes, int n_in,
                              void* d_out, int out_size) {
    const float* X     = (const float*)d_in[0];
    const float* dec   = (const float*)d_in[1];
    const float* W_enc = (const float*)d_in[2];
    const float* b_enc = (const float*)d_in[3];
    const float* W_dec = (const float*)d_in[4];
    const float* v_att = (const float*)d_in[5];
    const float* b_att = (const float*)d_in[6];

    float* ctx     = (float*)d_out;
    float* weights = (float*)d_out + B_ * E_;

    cudaFuncSetAttribute(scores_mma_kernel,
                         cudaFuncAttributeMaxDynamicSharedMemorySize, SMEM_TOTAL);

    convert_w_kernel<<<E_, A_>>>(W_enc);
    dproj_kernel<<<B_, A_>>>(dec, W_dec, b_enc);

    dim3 g1(T_ / 128, B_);
    scores_mma_kernel<<<g1, 512, SMEM_TOTAL>>>(X, v_att, b_att, weights);

    softmax_kernel<<<B_, 1024>>>(weights);

    dim3 g3(8, B_);
    cpart_kernel<<<g3, E_>>>(X, weights);
    creduce_kernel<<<(B_ * E_) / 256, 256>>>(ctx);
}

// round 6
// speedup vs baseline: 1.9563x; 1.9563x over previous
#include <cuda_runtime.h>
#include <cuda_fp16.h>
#include <cstdint>

#define B_  64
#define T_  4096
#define E_  512
#define A_  256

// ---------------------------------------------------------------------------
// scratch (allocation-free)
// ---------------------------------------------------------------------------
__device__ float g_dproj[B_ * A_];
__device__ float g_cpart[8 * B_ * E_];
__device__ __align__(128) __half g_Wf[A_ * E_];   // [n][k] K-major fp16

// ---------------------------------------------------------------------------
// helpers
// ---------------------------------------------------------------------------
__device__ __forceinline__ uint32_t smem_u32(const void* p) {
    uint32_t a;
    asm("{ .reg .u64 t; cvta.to.shared.u64 t, %1; cvt.u32.u64 %0, t; }" : "=r"(a) : "l"(p));
    return a;
}
__device__ __forceinline__ uint32_t swz128(uint32_t o) { return o ^ ((o >> 3) & 0x70); }

#define CP_ASYNC16(dst, src) \
    asm volatile("cp.async.cg.shared.global [%0], [%1], 16;" :: "r"(dst), "l"(src) : "memory")
#define CP_COMMIT()  asm volatile("cp.async.commit_group;" ::: "memory")
#define CP_WAIT1()   asm volatile("cp.async.wait_group 1;" ::: "memory")
#define CP_WAIT0()   asm volatile("cp.async.wait_group 0;" ::: "memory")

#define LDM4(r, a) \
    asm volatile("ldmatrix.sync.aligned.m8n8.x4.shared.b16 {%0,%1,%2,%3}, [%4];" \
        : "=r"((r)[0]), "=r"((r)[1]), "=r"((r)[2]), "=r"((r)[3]) : "r"(a))

__device__ __forceinline__ void mma_fp16(float* c, const uint32_t* a, const uint32_t* b) {
    asm volatile(
        "mma.sync.aligned.m16n8k16.row.col.f32.f16.f16.f32 "
        "{%0,%1,%2,%3}, {%4,%5,%6,%7}, {%8,%9}, {%0,%1,%2,%3};"
        : "+f"(c[0]), "+f"(c[1]), "+f"(c[2]), "+f"(c[3])
        : "r"(a[0]), "r"(a[1]), "r"(a[2]), "r"(a[3]), "r"(b[0]), "r"(b[1]));
}

// ---------------------------------------------------------------------------
// small prep kernels
// ---------------------------------------------------------------------------
__global__ void convert_w_kernel(const float* __restrict__ W) {
    int k = blockIdx.x;     // 512
    int n = threadIdx.x;    // 256
    g_Wf[n * E_ + k] = __float2half_rn(W[k * A_ + n]);
}

__global__ void dproj_kernel(const float* __restrict__ dec,
                             const float* __restrict__ Wd,
                             const float* __restrict__ b_enc) {
    int b = blockIdx.x;
    int a = threadIdx.x;
    const float* d = dec + b * E_;
    float s = b_enc[a];
    #pragma unroll 8
    for (int e = 0; e < E_; ++e)
        s = fmaf(d[e], Wd[e * A_ + a], s);
    g_dproj[b * A_ + a] = s;
}

// ---------------------------------------------------------------------------
// K1: single-pass fp16 HMMA scores GEMM, fused fp32->fp16 convert.
// CTA: M=128 x N=256, K=512 in 8 chunks of 64. 16 warps (4M x 4N), warp 32x64.
// smem: fp32 X stage (2x32K) | fp16 X tile 16K | fp16 W (2x32K) | epilogue.
// ---------------------------------------------------------------------------
#define KC       64
#define NCH      8
#define OFF_XF   0
#define OFF_XH   65536
#define OFF_W    81920
#define OFF_V    147456
#define OFF_DP   148480
#define OFF_RED  149504
#define SMEM_TOTAL 151552

__global__ void __launch_bounds__(512, 1)
scores_mma_kernel(const float* __restrict__ X,
                  const float* __restrict__ v_att,
                  const float* __restrict__ b_att,
                  float* __restrict__ scores)
{
    extern __shared__ char smem[];
    const uint32_t sb = smem_u32(smem);
    const int tid = threadIdx.x;
    const int lane = tid & 31, wid = tid >> 5;
    const int wm = wid >> 2, wn = wid & 3;      // 4 x 4 warp grid
    const int b = blockIdx.y;
    const int t0 = blockIdx.x * 128;

    float* vs  = (float*)(smem + OFF_V);
    float* dps = (float*)(smem + OFF_DP);
    float* red = (float*)(smem + OFF_RED);
    if (tid < 256) {
        vs[tid]  = v_att[tid];
        dps[tid] = g_dproj[b * A_ + tid];
    }

    const float* xrow = X + ((size_t)b * T_ + t0) * E_;

    float acc[2][8][4];
    #pragma unroll
    for (int mt = 0; mt < 2; ++mt)
        #pragma unroll
        for (int nt = 0; nt < 8; ++nt)
            #pragma unroll
            for (int e = 0; e < 4; ++e) acc[mt][nt][e] = 0.f;

    // per-lane ldmatrix base offsets (row*128 + 16B-half), swizzle applied per use
    const int rsel = lane & 15, chalf = lane >> 4;
    uint32_t abase[2], bbase[4];
    #pragma unroll
    for (int mt = 0; mt < 2; ++mt)
        abase[mt] = (uint32_t)(((wm << 5) + (mt << 4) + rsel) << 7) + (chalf << 4);
    #pragma unroll
    for (int n2 = 0; n2 < 4; ++n2)
        bbase[n2] = (uint32_t)(((wn << 6) + (n2 << 4) + rsel) << 7) + (chalf << 4);

    // chunk loader: fp32 X tile (128x64) + fp16 W tile (256x64)
    auto load_chunk = [&](int c) {
        const int kc = c * KC;
        const uint32_t s15 = (uint32_t)(c & 1) << 15;
        #pragma unroll
        for (int it = 0; it < 4; ++it) {           // X: 2048 x 16B, linear
            int i = tid + (it << 9);
            int r = i >> 4, q = i & 15;
            const float* src = xrow + (size_t)r * E_ + kc + (q << 2);
            CP_ASYNC16(sb + OFF_XF + s15 + (uint32_t)(i << 4), src);
        }
        #pragma unroll
        for (int it = 0; it < 4; ++it) {           // W: 2048 x 16B, SW128
            int i = tid + (it << 9);
            int r = i >> 3, q = i & 7;
            const __half* src = g_Wf + (size_t)r * E_ + kc + (q << 3);
            uint32_t dst = sb + OFF_W + s15 + swz128((r << 7) + (q << 4));
            CP_ASYNC16(dst, src);
        }
        CP_COMMIT();
    };

    load_chunk(0);

    for (int c = 0; c < NCH; ++c) {
        if (c + 1 < NCH) { load_chunk(c + 1); CP_WAIT1(); }
        else             { CP_WAIT0(); }
        __syncthreads();                           // stage c ready; XH free

        // convert fp32 stage -> swizzled fp16 X tile (1024 out-granules)
        {
            const char* xf = smem + OFF_XF + ((c & 1) << 15);
            #pragma unroll
            for (int it = 0; it < 2; ++it) {
                int g = tid + (it << 9);
                int r = g >> 3, q = g & 7;
                const char* srcp = xf + (r << 8) + (q << 5);
                float4 v0 = *(const float4*)(srcp);
                float4 v1 = *(const float4*)(srcp + 16);
                uint32_t p0 = (uint32_t)__half_as_ushort(__float2half_rn(v0.x)) |
                              ((uint32_t)__half_as_ushort(__float2half_rn(v0.y)) << 16);
                uint32_t p1 = (uint32_t)__half_as_ushort(__float2half_rn(v0.z)) |
                              ((uint32_t)__half_as_ushort(__float2half_rn(v0.w)) << 16);
                uint32_t p2 = (uint32_t)__half_as_ushort(__float2half_rn(v1.x)) |
                              ((uint32_t)__half_as_ushort(__float2half_rn(v1.y)) << 16);
                uint32_t p3 = (uint32_t)__half_as_ushort(__float2half_rn(v1.z)) |
                              ((uint32_t)__half_as_ushort(__float2half_rn(v1.w)) << 16);
                *(uint4*)(smem + OFF_XH + swz128((r << 7) + (q << 4))) =
                    make_uint4(p0, p1, p2, p3);
            }
        }
        __syncthreads();                           // XH ready

        const uint32_t xh = sb + OFF_XH;
        const uint32_t wb = sb + OFF_W + ((uint32_t)(c & 1) << 15);

        #pragma unroll
        for (int ks = 0; ks < 4; ++ks) {
            const uint32_t koff = ks << 5;
            uint32_t A[2][4], Bf[4][4];
            #pragma unroll
            for (int mt = 0; mt < 2; ++mt) LDM4(A[mt], xh + swz128(abase[mt] + koff));
            #pragma unroll
            for (int n2 = 0; n2 < 4; ++n2) LDM4(Bf[n2], wb + swz128(bbase[n2] + koff));
            #pragma unroll
            for (int n2 = 0; n2 < 4; ++n2) {
                uint32_t be[2] = { Bf[n2][0], Bf[n2][2] };
                uint32_t bo[2] = { Bf[n2][1], Bf[n2][3] };
                #pragma unroll
                for (int mt = 0; mt < 2; ++mt) {
                    mma_fp16(acc[mt][n2 * 2],     A[mt], be);
                    mma_fp16(acc[mt][n2 * 2 + 1], A[mt], bo);
                }
            }
        }
        __syncthreads();                           // done reading stage c
    }

    // epilogue: tanh + v dot, reduce within warp quads, then across wn
    const int g = lane >> 2, t = lane & 3;
    #pragma unroll
    for (int mt = 0; mt < 2; ++mt) {
        float pa = 0.f, pb = 0.f;
        #pragma unroll
        for (int nt = 0; nt < 8; ++nt) {
            int col = (wn << 6) + (nt << 3) + (t << 1);
            float v0 = vs[col], v1 = vs[col + 1];
            float d0 = dps[col], d1 = dps[col + 1];
            pa = fmaf(v0, tanhf(acc[mt][nt][0] + d0), pa);
            pa = fmaf(v1, tanhf(acc[mt][nt][1] + d1), pa);
            pb = fmaf(v0, tanhf(acc[mt][nt][2] + d0), pb);
            pb = fmaf(v1, tanhf(acc[mt][nt][3] + d1), pb);
        }
        pa += __shfl_xor_sync(0xffffffffu, pa, 1);
        pa += __shfl_xor_sync(0xffffffffu, pa, 2);
        pb += __shfl_xor_sync(0xffffffffu, pb, 1);
        pb += __shfl_xor_sync(0xffffffffu, pb, 2);
        if (t == 0) {
            int row = (wm << 5) + (mt << 4) + g;
            red[row * 4 + wn]       = pa;
            red[(row + 8) * 4 + wn] = pb;
        }
    }
    __syncthreads();

    if (tid < 128) {
        float s = red[tid * 4] + red[tid * 4 + 1] + red[tid * 4 + 2] + red[tid * 4 + 3];
        scores[(size_t)b * T_ + t0 + tid] = s + b_att[0];
    }
}

// ---------------------------------------------------------------------------
// K2: softmax over T per batch
// ---------------------------------------------------------------------------
__global__ void softmax_kernel(float* __restrict__ w) {
    const int b = blockIdx.x;
    float* row = w + (size_t)b * T_;
    const int tid = threadIdx.x, lane = tid & 31, wd = tid >> 5;
    __shared__ float sm[32];
    __shared__ float s_b;

    float v[4];
    float m = -1e30f;
    #pragma unroll
    for (int i = 0; i < 4; ++i) { v[i] = row[tid + (i << 10)]; m = fmaxf(m, v[i]); }
    #pragma unroll
    for (int o = 16; o; o >>= 1) m = fmaxf(m, __shfl_xor_sync(0xffffffffu, m, o));
    if (lane == 0) sm[wd] = m;
    __syncthreads();
    if (tid < 32) {
        float t = sm[tid];
        #pragma unroll
        for (int o = 16; o; o >>= 1) t = fmaxf(t, __shfl_xor_sync(0xffffffffu, t, o));
        if (tid == 0) s_b = t;
    }
    __syncthreads();
    const float mx = s_b;

    float s = 0.f;
    #pragma unroll
    for (int i = 0; i < 4; ++i) { v[i] = __expf(v[i] - mx); s += v[i]; }
    #pragma unroll
    for (int o = 16; o; o >>= 1) s += __shfl_xor_sync(0xffffffffu, s, o);
    if (lane == 0) sm[wd] = s;
    __syncthreads();
    if (tid < 32) {
        float t = sm[tid];
        #pragma unroll
        for (int o = 16; o; o >>= 1) t += __shfl_xor_sync(0xffffffffu, t, o);
        if (tid == 0) s_b = t;
    }
    __syncthreads();
    const float inv = 1.0f / s_b;
    #pragma unroll
    for (int i = 0; i < 4; ++i) row[tid + (i << 10)] = v[i] * inv;
}

// ---------------------------------------------------------------------------
// K3/K4: context
// ---------------------------------------------------------------------------
__global__ void cpart_kernel(const float* __restrict__ X,
                             const float* __restrict__ w) {
    const int c = blockIdx.x, b = blockIdx.y, e = threadIdx.x;
    const float* xb = X + ((size_t)b * T_ + (size_t)c * 512) * E_ + e;
    const float* wb = w + (size_t)b * T_ + (size_t)c * 512;
    float a[8] = {0,0,0,0,0,0,0,0};
    #pragma unroll 2
    for (int t = 0; t < 512; t += 8) {
        #pragma unroll
        for (int u = 0; u < 8; ++u)
            a[u] = fmaf(wb[t + u], xb[(size_t)(t + u) * E_], a[u]);
    }
    g_cpart[((size_t)c * B_ + b) * E_ + e] =
        ((a[0] + a[1]) + (a[2] + a[3])) + ((a[4] + a[5]) + (a[6] + a[7]));
}

__global__ void creduce_kernel(float* __restrict__ ctx) {
    int i = blockIdx.x * blockDim.x + threadIdx.x;
    int b = i >> 9, e = i & 511;
    float s = 0.f;
    #pragma unroll
    for (int c = 0; c < 8; ++c)
        s += g_cpart[((size_t)c * B_ + b) * E_ + e];
    ctx[i] = s;
}

// ---------------------------------------------------------------------------
extern "C" void kernel_launch(void* const* d_in, const int* in_sizes, int n_in,
                              void* d_out, int out_size) {
    const float* X     = (const float*)d_in[0];
    const float* dec   = (const float*)d_in[1];
    const float* W_enc = (const float*)d_in[2];
    const float* b_enc = (const float*)d_in[3];
    const float* W_dec = (const float*)d_in[4];
    const float* v_att = (const float*)d_in[5];
    const float* b_att = (const float*)d_in[6];

    float* ctx     = (float*)d_out;
    float* weights = (float*)d_out + B_ * E_;

    cudaFuncSetAttribute(scores_mma_kernel,
                         cudaFuncAttributeMaxDynamicSharedMemorySize, SMEM_TOTAL);

    convert_w_kernel<<<E_, A_>>>(W_enc);
    dproj_kernel<<<B_, A_>>>(dec, W_dec, b_enc);

    dim3 g1(T_ / 128, B_);
    scores_mma_kernel<<<g1, 512, SMEM_TOTAL>>>(X, v_att, b_att, weights);

    softmax_kernel<<<B_, 1024>>>(weights);

    dim3 g3(8, B_);
    cpart_kernel<<<g3, E_>>>(X, weights);
    creduce_kernel<<<(B_ * E_) / 256, 256>>>(ctx);
}

// round 7
// speedup vs baseline: 2.2107x; 1.1300x over previous
#include <cuda_runtime.h>
#include <cuda_fp16.h>
#include <cstdint>

#define B_  64
#define T_  4096
#define E_  512
#define A_  256
#define CPB 32                     // CTAs per batch (T/128)

// ---------------------------------------------------------------------------
// scratch (allocation-free)
// ---------------------------------------------------------------------------
__device__ float g_dproj[B_ * A_];
__device__ float g_P[(size_t)B_ * CPB * E_];       // partial contexts, 4MB
__device__ float g_m[B_ * CPB];                    // per-CTA local max
__device__ float g_s[B_ * CPB];                    // per-CTA local expsum
__device__ __align__(128) __half g_Wf[A_ * E_];    // [n][k] K-major fp16

// ---------------------------------------------------------------------------
// helpers
// ---------------------------------------------------------------------------
__device__ __forceinline__ uint32_t smem_u32(const void* p) {
    uint32_t a;
    asm("{ .reg .u64 t; cvta.to.shared.u64 t, %1; cvt.u32.u64 %0, t; }" : "=r"(a) : "l"(p));
    return a;
}
__device__ __forceinline__ uint32_t swz128(uint32_t o) { return o ^ ((o >> 3) & 0x70); }

#define CP_ASYNC16(dst, src) \
    asm volatile("cp.async.cg.shared.global [%0], [%1], 16;" :: "r"(dst), "l"(src) : "memory")
#define CP_COMMIT()  asm volatile("cp.async.commit_group;" ::: "memory")
#define CP_WAIT1()   asm volatile("cp.async.wait_group 1;" ::: "memory")
#define CP_WAIT0()   asm volatile("cp.async.wait_group 0;" ::: "memory")

#define LDM4(r, a) \
    asm volatile("ldmatrix.sync.aligned.m8n8.x4.shared.b16 {%0,%1,%2,%3}, [%4];" \
        : "=r"((r)[0]), "=r"((r)[1]), "=r"((r)[2]), "=r"((r)[3]) : "r"(a))

__device__ __forceinline__ void mma_fp16(float* c, const uint32_t* a, const uint32_t* b) {
    asm volatile(
        "mma.sync.aligned.m16n8k16.row.col.f32.f16.f16.f32 "
        "{%0,%1,%2,%3}, {%4,%5,%6,%7}, {%8,%9}, {%0,%1,%2,%3};"
        : "+f"(c[0]), "+f"(c[1]), "+f"(c[2]), "+f"(c[3])
        : "r"(a[0]), "r"(a[1]), "r"(a[2]), "r"(a[3]), "r"(b[0]), "r"(b[1]));
}

// ---------------------------------------------------------------------------
// small prep kernels
// ---------------------------------------------------------------------------
__global__ void convert_w_kernel(const float* __restrict__ W) {
    int k = blockIdx.x;     // 512
    int n = threadIdx.x;    // 256
    g_Wf[n * E_ + k] = __float2half_rn(W[k * A_ + n]);
}

__global__ void dproj_kernel(const float* __restrict__ dec,
                             const float* __restrict__ Wd,
                             const float* __restrict__ b_enc) {
    int b = blockIdx.x;
    int a = threadIdx.x;
    const float* d = dec + b * E_;
    float s = b_enc[a];
    #pragma unroll 8
    for (int e = 0; e < E_; ++e)
        s = fmaf(d[e], Wd[e * A_ + a], s);
    g_dproj[b * A_ + a] = s;
}

// ---------------------------------------------------------------------------
// K1: fused fp16 HMMA scores GEMM + local softmax + partial context.
// CTA: M=128 x N=256, K=512 in 8 chunks of 64. 16 warps (4M x 4N), warp 32x64.
// Outputs per CTA: unnormalized u_t -> weights, (m_c, S_c), P_c[512].
// ---------------------------------------------------------------------------
#define KC       64
#define NCH      8
#define OFF_XF   0
#define OFF_XH   65536
#define OFF_W    81920
#define OFF_V    147456
#define OFF_DP   148480
#define OFF_RED  149504                 // 128 x 4 floats
#define OFF_U    151552                 // 128 floats (u_t)
#define OFF_RW   152064                 // 16 + 16 + 2 floats reduce scratch
#define SMEM_TOTAL 152576

__global__ void __launch_bounds__(512, 1)
scores_mma_kernel(const float* __restrict__ X,
                  const float* __restrict__ v_att,
                  const float* __restrict__ b_att,
                  float* __restrict__ weights)
{
    extern __shared__ char smem[];
    const uint32_t sb = smem_u32(smem);
    const int tid = threadIdx.x;
    const int lane = tid & 31, wid = tid >> 5;
    const int wm = wid >> 2, wn = wid & 3;      // 4 x 4 warp grid
    const int b = blockIdx.y;
    const int t0 = blockIdx.x * 128;
    const int cta = b * CPB + blockIdx.x;

    float* vs   = (float*)(smem + OFF_V);
    float* dps  = (float*)(smem + OFF_DP);
    float* red  = (float*)(smem + OFF_RED);
    float* usm  = (float*)(smem + OFF_U);
    float* rmax = (float*)(smem + OFF_RW);       // [16]
    float* rsum = rmax + 16;                     // [16]
    float* rsc  = rsum + 16;                     // [2]: m_c
    if (tid < 256) {
        vs[tid]  = v_att[tid];
        dps[tid] = g_dproj[b * A_ + tid];
    }

    const float* xrow = X + ((size_t)b * T_ + t0) * E_;

    float acc[2][8][4];
    #pragma unroll
    for (int mt = 0; mt < 2; ++mt)
        #pragma unroll
        for (int nt = 0; nt < 8; ++nt)
            #pragma unroll
            for (int e = 0; e < 4; ++e) acc[mt][nt][e] = 0.f;

    // per-lane ldmatrix base offsets
    const int rsel = lane & 15, chalf = lane >> 4;
    uint32_t abase[2], bbase[4];
    #pragma unroll
    for (int mt = 0; mt < 2; ++mt)
        abase[mt] = (uint32_t)(((wm << 5) + (mt << 4) + rsel) << 7) + (chalf << 4);
    #pragma unroll
    for (int n2 = 0; n2 < 4; ++n2)
        bbase[n2] = (uint32_t)(((wn << 6) + (n2 << 4) + rsel) << 7) + (chalf << 4);

    // chunk loader: fp32 X tile (128x64) + fp16 W tile (256x64)
    auto load_chunk = [&](int c) {
        const int kc = c * KC;
        const uint32_t s15 = (uint32_t)(c & 1) << 15;
        #pragma unroll
        for (int it = 0; it < 4; ++it) {           // X: 2048 x 16B, linear
            int i = tid + (it << 9);
            int r = i >> 4, q = i & 15;
            const float* src = xrow + (size_t)r * E_ + kc + (q << 2);
            CP_ASYNC16(sb + OFF_XF + s15 + (uint32_t)(i << 4), src);
        }
        #pragma unroll
        for (int it = 0; it < 4; ++it) {           // W: 2048 x 16B, SW128
            int i = tid + (it << 9);
            int r = i >> 3, q = i & 7;
            const __half* src = g_Wf + (size_t)r * E_ + kc + (q << 3);
            uint32_t dst = sb + OFF_W + s15 + swz128((r << 7) + (q << 4));
            CP_ASYNC16(dst, src);
        }
        CP_COMMIT();
    };

    load_chunk(0);

    for (int c = 0; c < NCH; ++c) {
        if (c + 1 < NCH) { load_chunk(c + 1); CP_WAIT1(); }
        else             { CP_WAIT0(); }
        __syncthreads();                           // stage c ready; XH free

        // convert fp32 stage -> swizzled fp16 X tile
        {
            const char* xf = smem + OFF_XF + ((c & 1) << 15);
            #pragma unroll
            for (int it = 0; it < 2; ++it) {
                int g = tid + (it << 9);
                int r = g >> 3, q = g & 7;
                const char* srcp = xf + (r << 8) + (q << 5);
                float4 v0 = *(const float4*)(srcp);
                float4 v1 = *(const float4*)(srcp + 16);
                uint32_t p0 = (uint32_t)__half_as_ushort(__float2half_rn(v0.x)) |
                              ((uint32_t)__half_as_ushort(__float2half_rn(v0.y)) << 16);
                uint32_t p1 = (uint32_t)__half_as_ushort(__float2half_rn(v0.z)) |
                              ((uint32_t)__half_as_ushort(__float2half_rn(v0.w)) << 16);
                uint32_t p2 = (uint32_t)__half_as_ushort(__float2half_rn(v1.x)) |
                              ((uint32_t)__half_as_ushort(__float2half_rn(v1.y)) << 16);
                uint32_t p3 = (uint32_t)__half_as_ushort(__float2half_rn(v1.z)) |
                              ((uint32_t)__half_as_ushort(__float2half_rn(v1.w)) << 16);
                *(uint4*)(smem + OFF_XH + swz128((r << 7) + (q << 4))) =
                    make_uint4(p0, p1, p2, p3);
            }
        }
        __syncthreads();                           // XH ready

        const uint32_t xh = sb + OFF_XH;
        const uint32_t wb = sb + OFF_W + ((uint32_t)(c & 1) << 15);

        #pragma unroll
        for (int ks = 0; ks < 4; ++ks) {
            const uint32_t koff = ks << 5;
            uint32_t A[2][4], Bf[4][4];
            #pragma unroll
            for (int mt = 0; mt < 2; ++mt) LDM4(A[mt], xh + swz128(abase[mt] + koff));
            #pragma unroll
            for (int n2 = 0; n2 < 4; ++n2) LDM4(Bf[n2], wb + swz128(bbase[n2] + koff));
            #pragma unroll
            for (int n2 = 0; n2 < 4; ++n2) {
                uint32_t be[2] = { Bf[n2][0], Bf[n2][2] };
                uint32_t bo[2] = { Bf[n2][1], Bf[n2][3] };
                #pragma unroll
                for (int mt = 0; mt < 2; ++mt) {
                    mma_fp16(acc[mt][n2 * 2],     A[mt], be);
                    mma_fp16(acc[mt][n2 * 2 + 1], A[mt], bo);
                }
            }
        }
        __syncthreads();                           // done reading stage c
    }

    // ---- epilogue: tanh + v dot, reduce to per-row score ----
    const int g = lane >> 2, t = lane & 3;
    #pragma unroll
    for (int mt = 0; mt < 2; ++mt) {
        float pa = 0.f, pb = 0.f;
        #pragma unroll
        for (int nt = 0; nt < 8; ++nt) {
            int col = (wn << 6) + (nt << 3) + (t << 1);
            float v0 = vs[col], v1 = vs[col + 1];
            float d0 = dps[col], d1 = dps[col + 1];
            pa = fmaf(v0, tanhf(acc[mt][nt][0] + d0), pa);
            pa = fmaf(v1, tanhf(acc[mt][nt][1] + d1), pa);
            pb = fmaf(v0, tanhf(acc[mt][nt][2] + d0), pb);
            pb = fmaf(v1, tanhf(acc[mt][nt][3] + d1), pb);
        }
        pa += __shfl_xor_sync(0xffffffffu, pa, 1);
        pa += __shfl_xor_sync(0xffffffffu, pa, 2);
        pb += __shfl_xor_sync(0xffffffffu, pb, 1);
        pb += __shfl_xor_sync(0xffffffffu, pb, 2);
        if (t == 0) {
            int row = (wm << 5) + (mt << 4) + g;
            red[row * 4 + wn]       = pa;
            red[(row + 8) * 4 + wn] = pb;
        }
    }
    __syncthreads();

    // ---- local softmax: m_c, u_t, S_c ----
    float sval = -1e30f;
    if (tid < 128)
        sval = red[tid * 4] + red[tid * 4 + 1] + red[tid * 4 + 2] + red[tid * 4 + 3]
             + b_att[0];
    float wmx = sval;
    #pragma unroll
    for (int o = 16; o; o >>= 1) wmx = fmaxf(wmx, __shfl_xor_sync(0xffffffffu, wmx, o));
    if (lane == 0) rmax[wid] = wmx;
    __syncthreads();
    if (tid == 0)
        rsc[0] = fmaxf(fmaxf(rmax[0], rmax[1]), fmaxf(rmax[2], rmax[3]));
    __syncthreads();
    const float m_c = rsc[0];

    float u = (tid < 128) ? __expf(sval - m_c) : 0.f;
    if (tid < 128) {
        usm[tid] = u;
        weights[(size_t)b * T_ + t0 + tid] = u;    // unnormalized; fixed in combine
    }
    float wsum = u;
    #pragma unroll
    for (int o = 16; o; o >>= 1) wsum += __shfl_xor_sync(0xffffffffu, wsum, o);
    if (lane == 0) rsum[wid] = wsum;
    __syncthreads();
    if (tid == 0) {
        g_m[cta] = m_c;
        g_s[cta] = rsum[0] + rsum[1] + rsum[2] + rsum[3];
    }
    __syncthreads();

    // ---- partial context: P_c[e] = sum_t u_t * X[t, e] ----
    {
        const float* xp = xrow + tid;              // e = tid, coalesced
        float a0 = 0.f, a1 = 0.f, a2 = 0.f, a3 = 0.f;
        #pragma unroll 4
        for (int tt = 0; tt < 128; tt += 4) {
            a0 = fmaf(usm[tt + 0], xp[(size_t)(tt + 0) * E_], a0);
            a1 = fmaf(usm[tt + 1], xp[(size_t)(tt + 1) * E_], a1);
            a2 = fmaf(usm[tt + 2], xp[(size_t)(tt + 2) * E_], a2);
            a3 = fmaf(usm[tt + 3], xp[(size_t)(tt + 3) * E_], a3);
        }
        g_P[(size_t)cta * E_ + tid] = (a0 + a1) + (a2 + a3);
    }
}

// ---------------------------------------------------------------------------
// K2: combine — cross-CTA softmax algebra, context, weight rescale.
// grid = B_, block = 512.
// ---------------------------------------------------------------------------
__global__ void combine_kernel(float* __restrict__ ctx,
                               float* __restrict__ weights)
{
    const int b = blockIdx.x;
    const int tid = threadIdx.x;
    __shared__ float alpha[CPB];

    if (tid < CPB) {
        float m = g_m[b * CPB + tid];
        float M = m;
        #pragma unroll
        for (int o = 16; o; o >>= 1) M = fmaxf(M, __shfl_xor_sync(0xffffffffu, M, o));
        float e = __expf(m - M);
        float s = g_s[b * CPB + tid] * e;
        float S = s;
        #pragma unroll
        for (int o = 16; o; o >>= 1) S += __shfl_xor_sync(0xffffffffu, S, o);
        alpha[tid] = e / S;
    }
    __syncthreads();

    // context: e = tid
    {
        float a = 0.f;
        const float* P = g_P + (size_t)b * CPB * E_ + tid;
        #pragma unroll 8
        for (int c = 0; c < CPB; ++c)
            a = fmaf(P[(size_t)c * E_], alpha[c], a);
        ctx[(size_t)b * E_ + tid] = a;
    }
    // weights rescale
    {
        float* w = weights + (size_t)b * T_;
        #pragma unroll
        for (int i = tid; i < T_; i += 512)
            w[i] *= alpha[i >> 7];
    }
}

// ---------------------------------------------------------------------------
extern "C" void kernel_launch(void* const* d_in, const int* in_sizes, int n_in,
                              void* d_out, int out_size) {
    const float* X     = (const float*)d_in[0];
    const float* dec   = (const float*)d_in[1];
    const float* W_enc = (const float*)d_in[2];
    const float* b_enc = (const float*)d_in[3];
    const float* W_dec = (const float*)d_in[4];
    const float* v_att = (const float*)d_in[5];
    const float* b_att = (const float*)d_in[6];

    float* ctx     = (float*)d_out;
    float* weights = (float*)d_out + B_ * E_;

    cudaFuncSetAttribute(scores_mma_kernel,
                         cudaFuncAttributeMaxDynamicSharedMemorySize, SMEM_TOTAL);

    convert_w_kernel<<<E_, A_>>>(W_enc);
    dproj_kernel<<<B_, A_>>>(dec, W_dec, b_enc);

    dim3 g1(T_ / 128, B_);
    scores_mma_kernel<<<g1, 512, SMEM_TOTAL>>>(X, v_att, b_att, weights);

    combine_kernel<<<B_, 512>>>(ctx, weights);
}

// round 8
// speedup vs baseline: 2.4403x; 1.1039x over previous
#include <cuda_runtime.h>
#include <cuda_fp16.h>
#include <cstdint>

#define B_  64
#define T_  4096
#define E_  512
#define A_  256
#define CPB 64                     // CTAs per batch (T/64)

// ---------------------------------------------------------------------------
// scratch (allocation-free)
// ---------------------------------------------------------------------------
__device__ float g_dproj[B_ * A_];
__device__ float g_P[(size_t)B_ * CPB * E_];       // partial contexts, 8MB
__device__ float g_m[B_ * CPB];                    // per-CTA local max
__device__ float g_s[B_ * CPB];                    // per-CTA local expsum
__device__ __align__(128) __half g_Wf[A_ * E_];    // [n][k] K-major fp16

// ---------------------------------------------------------------------------
// helpers
// ---------------------------------------------------------------------------
__device__ __forceinline__ uint32_t smem_u32(const void* p) {
    uint32_t a;
    asm("{ .reg .u64 t; cvta.to.shared.u64 t, %1; cvt.u32.u64 %0, t; }" : "=r"(a) : "l"(p));
    return a;
}
__device__ __forceinline__ uint32_t swz128(uint32_t o) { return o ^ ((o >> 3) & 0x70); }

#define CP_ASYNC16(dst, src) \
    asm volatile("cp.async.cg.shared.global [%0], [%1], 16;" :: "r"(dst), "l"(src) : "memory")
#define CP_COMMIT()  asm volatile("cp.async.commit_group;" ::: "memory")
#define CP_WAIT1()   asm volatile("cp.async.wait_group 1;" ::: "memory")
#define CP_WAIT0()   asm volatile("cp.async.wait_group 0;" ::: "memory")

#define LDM4(r, a) \
    asm volatile("ldmatrix.sync.aligned.m8n8.x4.shared.b16 {%0,%1,%2,%3}, [%4];" \
        : "=r"((r)[0]), "=r"((r)[1]), "=r"((r)[2]), "=r"((r)[3]) : "r"(a))

__device__ __forceinline__ void mma_fp16(float* c, const uint32_t* a, const uint32_t* b) {
    asm volatile(
        "mma.sync.aligned.m16n8k16.row.col.f32.f16.f16.f32 "
        "{%0,%1,%2,%3}, {%4,%5,%6,%7}, {%8,%9}, {%0,%1,%2,%3};"
        : "+f"(c[0]), "+f"(c[1]), "+f"(c[2]), "+f"(c[3])
        : "r"(a[0]), "r"(a[1]), "r"(a[2]), "r"(a[3]), "r"(b[0]), "r"(b[1]));
}

// ---------------------------------------------------------------------------
// small prep kernels
// ---------------------------------------------------------------------------
__global__ void convert_w_kernel(const float* __restrict__ W) {
    int k = blockIdx.x;     // 512
    int n = threadIdx.x;    // 256
    g_Wf[n * E_ + k] = __float2half_rn(W[k * A_ + n]);
}

__global__ void dproj_kernel(const float* __restrict__ dec,
                             const float* __restrict__ Wd,
                             const float* __restrict__ b_enc) {
    int b = blockIdx.x;
    int a = threadIdx.x;
    const float* d = dec + b * E_;
    float s = b_enc[a];
    #pragma unroll 8
    for (int e = 0; e < E_; ++e)
        s = fmaf(d[e], Wd[e * A_ + a], s);
    g_dproj[b * A_ + a] = s;
}

// ---------------------------------------------------------------------------
// K1: fused fp16 HMMA scores GEMM + local softmax + partial context.
// CTA: M=64 x N=256, K=512 in 8 chunks of 64. 8 warps (2M x 4N), warp 32x64.
// 256 threads, smem 110KB -> 2 CTAs/SM so phases overlap across CTAs.
// ---------------------------------------------------------------------------
#define KC       64
#define NCH      8
#define OFF_XF   0                      // 2 x 16KB fp32 stage
#define OFF_XH   32768                  // 8KB fp16 X tile
#define OFF_W    40960                  // 2 x 32KB fp16 W
#define OFF_V    106496
#define OFF_DP   107520
#define OFF_RED  108544                 // 64 x 4 floats
#define OFF_U    109568                 // 64 floats
#define OFF_RW   109824                 // reduce scratch
#define SMEM_TOTAL 110080

__global__ void __launch_bounds__(256, 2)
scores_mma_kernel(const float* __restrict__ X,
                  const float* __restrict__ v_att,
                  const float* __restrict__ b_att,
                  float* __restrict__ weights)
{
    extern __shared__ char smem[];
    const uint32_t sb = smem_u32(smem);
    const int tid = threadIdx.x;
    const int lane = tid & 31, wid = tid >> 5;
    const int wm = wid >> 2, wn = wid & 3;      // 2 x 4 warp grid
    const int b = blockIdx.y;
    const int t0 = blockIdx.x * 64;
    const int cta = b * CPB + blockIdx.x;

    float* vs   = (float*)(smem + OFF_V);
    float* dps  = (float*)(smem + OFF_DP);
    float* red  = (float*)(smem + OFF_RED);
    float* usm  = (float*)(smem + OFF_U);
    float* rmax = (float*)(smem + OFF_RW);       // [8]
    float* rsum = rmax + 8;                      // [8]
    float* rsc  = rsum + 8;                      // [1]
    vs[tid]  = v_att[tid];
    dps[tid] = g_dproj[b * A_ + tid];

    const float* xrow = X + ((size_t)b * T_ + t0) * E_;

    float acc[2][8][4];
    #pragma unroll
    for (int mt = 0; mt < 2; ++mt)
        #pragma unroll
        for (int nt = 0; nt < 8; ++nt)
            #pragma unroll
            for (int e = 0; e < 4; ++e) acc[mt][nt][e] = 0.f;

    // per-lane ldmatrix base offsets
    const int rsel = lane & 15, chalf = lane >> 4;
    uint32_t abase[2], bbase[4];
    #pragma unroll
    for (int mt = 0; mt < 2; ++mt)
        abase[mt] = (uint32_t)(((wm << 5) + (mt << 4) + rsel) << 7) + (chalf << 4);
    #pragma unroll
    for (int n2 = 0; n2 < 4; ++n2)
        bbase[n2] = (uint32_t)(((wn << 6) + (n2 << 4) + rsel) << 7) + (chalf << 4);

    // chunk loader: fp32 X tile (64x64) + fp16 W tile (256x64)
    auto load_chunk = [&](int c) {
        const int kc = c * KC;
        const uint32_t s14 = (uint32_t)(c & 1) << 14;   // X stage stride 16KB
        const uint32_t s15 = (uint32_t)(c & 1) << 15;   // W stage stride 32KB
        #pragma unroll
        for (int it = 0; it < 4; ++it) {           // X: 1024 x 16B, linear
            int i = tid + (it << 8);
            int r = i >> 4, q = i & 15;
            const float* src = xrow + (size_t)r * E_ + kc + (q << 2);
            CP_ASYNC16(sb + OFF_XF + s14 + (uint32_t)(i << 4), src);
        }
        #pragma unroll
        for (int it = 0; it < 8; ++it) {           // W: 2048 x 16B, SW128
            int i = tid + (it << 8);
            int r = i >> 3, q = i & 7;
            const __half* src = g_Wf + (size_t)r * E_ + kc + (q << 3);
            uint32_t dst = sb + OFF_W + s15 + swz128((r << 7) + (q << 4));
            CP_ASYNC16(dst, src);
        }
        CP_COMMIT();
    };

    load_chunk(0);

    for (int c = 0; c < NCH; ++c) {
        if (c + 1 < NCH) { load_chunk(c + 1); CP_WAIT1(); }
        else             { CP_WAIT0(); }
        __syncthreads();                           // stage c ready; XH free

        // convert fp32 stage -> swizzled fp16 X tile (512 out-granules)
        {
            const char* xf = smem + OFF_XF + ((c & 1) << 14);
            #pragma unroll
            for (int it = 0; it < 2; ++it) {
                int g = tid + (it << 8);
                int r = g >> 3, q = g & 7;
                const char* srcp = xf + (r << 8) + (q << 5);
                float4 v0 = *(const float4*)(srcp);
                float4 v1 = *(const float4*)(srcp + 16);
                uint32_t p0 = (uint32_t)__half_as_ushort(__float2half_rn(v0.x)) |
                              ((uint32_t)__half_as_ushort(__float2half_rn(v0.y)) << 16);
                uint32_t p1 = (uint32_t)__half_as_ushort(__float2half_rn(v0.z)) |
                              ((uint32_t)__half_as_ushort(__float2half_rn(v0.w)) << 16);
                uint32_t p2 = (uint32_t)__half_as_ushort(__float2half_rn(v1.x)) |
                              ((uint32_t)__half_as_ushort(__float2half_rn(v1.y)) << 16);
                uint32_t p3 = (uint32_t)__half_as_ushort(__float2half_rn(v1.z)) |
                              ((uint32_t)__half_as_ushort(__float2half_rn(v1.w)) << 16);
                *(uint4*)(smem + OFF_XH + swz128((r << 7) + (q << 4))) =
                    make_uint4(p0, p1, p2, p3);
            }
        }
        __syncthreads();                           // XH ready

        const uint32_t xh = sb + OFF_XH;
        const uint32_t wb = sb + OFF_W + ((uint32_t)(c & 1) << 15);

        #pragma unroll
        for (int ks = 0; ks < 4; ++ks) {
            const uint32_t koff = ks << 5;
            uint32_t A[2][4], Bf[4][4];
            #pragma unroll
            for (int mt = 0; mt < 2; ++mt) LDM4(A[mt], xh + swz128(abase[mt] + koff));
            #pragma unroll
            for (int n2 = 0; n2 < 4; ++n2) LDM4(Bf[n2], wb + swz128(bbase[n2] + koff));
            #pragma unroll
            for (int n2 = 0; n2 < 4; ++n2) {
                uint32_t be[2] = { Bf[n2][0], Bf[n2][2] };
                uint32_t bo[2] = { Bf[n2][1], Bf[n2][3] };
                #pragma unroll
                for (int mt = 0; mt < 2; ++mt) {
                    mma_fp16(acc[mt][n2 * 2],     A[mt], be);
                    mma_fp16(acc[mt][n2 * 2 + 1], A[mt], bo);
                }
            }
        }
        __syncthreads();                           // done reading stage c
    }

    // ---- epilogue: tanh + v dot, reduce to per-row score ----
    const int g = lane >> 2, t = lane & 3;
    #pragma unroll
    for (int mt = 0; mt < 2; ++mt) {
        float pa = 0.f, pb = 0.f;
        #pragma unroll
        for (int nt = 0; nt < 8; ++nt) {
            int col = (wn << 6) + (nt << 3) + (t << 1);
            float v0 = vs[col], v1 = vs[col + 1];
            float d0 = dps[col], d1 = dps[col + 1];
            pa = fmaf(v0, tanhf(acc[mt][nt][0] + d0), pa);
            pa = fmaf(v1, tanhf(acc[mt][nt][1] + d1), pa);
            pb = fmaf(v0, tanhf(acc[mt][nt][2] + d0), pb);
            pb = fmaf(v1, tanhf(acc[mt][nt][3] + d1), pb);
        }
        pa += __shfl_xor_sync(0xffffffffu, pa, 1);
        pa += __shfl_xor_sync(0xffffffffu, pa, 2);
        pb += __shfl_xor_sync(0xffffffffu, pb, 1);
        pb += __shfl_xor_sync(0xffffffffu, pb, 2);
        if (t == 0) {
            int row = (wm << 5) + (mt << 4) + g;
            red[row * 4 + wn]       = pa;
            red[(row + 8) * 4 + wn] = pb;
        }
    }
    __syncthreads();

    // ---- local softmax over 64 rows: m_c, u_t, S_c ----
    float sval = -1e30f;
    if (tid < 64)
        sval = red[tid * 4] + red[tid * 4 + 1] + red[tid * 4 + 2] + red[tid * 4 + 3]
             + b_att[0];
    float wmx = sval;
    #pragma unroll
    for (int o = 16; o; o >>= 1) wmx = fmaxf(wmx, __shfl_xor_sync(0xffffffffu, wmx, o));
    if (lane == 0 && wid < 2) rmax[wid] = wmx;
    __syncthreads();
    if (tid == 0) rsc[0] = fmaxf(rmax[0], rmax[1]);
    __syncthreads();
    const float m_c = rsc[0];

    float u = (tid < 64) ? __expf(sval - m_c) : 0.f;
    if (tid < 64) {
        usm[tid] = u;
        weights[(size_t)b * T_ + t0 + tid] = u;    // unnormalized; fixed in combine
    }
    float wsum = u;
    #pragma unroll
    for (int o = 16; o; o >>= 1) wsum += __shfl_xor_sync(0xffffffffu, wsum, o);
    if (lane == 0 && wid < 2) rsum[wid] = wsum;
    __syncthreads();
    if (tid == 0) {
        g_m[cta] = m_c;
        g_s[cta] = rsum[0] + rsum[1];
    }
    __syncthreads();

    // ---- partial context: P_c[e] = sum_t u_t * X[t, e], e = tid, tid+256 ----
    #pragma unroll
    for (int half = 0; half < 2; ++half) {
        const float* xp = xrow + tid + (half << 8);
        float a0 = 0.f, a1 = 0.f, a2 = 0.f, a3 = 0.f;
        #pragma unroll 4
        for (int tt = 0; tt < 64; tt += 4) {
            a0 = fmaf(usm[tt + 0], xp[(size_t)(tt + 0) * E_], a0);
            a1 = fmaf(usm[tt + 1], xp[(size_t)(tt + 1) * E_], a1);
            a2 = fmaf(usm[tt + 2], xp[(size_t)(tt + 2) * E_], a2);
            a3 = fmaf(usm[tt + 3], xp[(size_t)(tt + 3) * E_], a3);
        }
        g_P[(size_t)cta * E_ + tid + (half << 8)] = (a0 + a1) + (a2 + a3);
    }
}

// ---------------------------------------------------------------------------
// K2: combine — cross-CTA softmax algebra, context, weight rescale.
// grid = B_, block = 512.
// ---------------------------------------------------------------------------
__global__ void combine_kernel(float* __restrict__ ctx,
                               float* __restrict__ weights)
{
    const int b = blockIdx.x;
    const int tid = threadIdx.x;
    const int lane = tid & 31, wid = tid >> 5;
    __shared__ float alpha[CPB];
    __shared__ float wm2[2], ws2[2];

    float m = -1e30f, s = 0.f;
    if (tid < CPB) {
        m = g_m[b * CPB + tid];
        s = g_s[b * CPB + tid];
    }
    if (tid < CPB) {
        float M = m;
        #pragma unroll
        for (int o = 16; o; o >>= 1) M = fmaxf(M, __shfl_xor_sync(0xffffffffu, M, o));
        if (lane == 0) wm2[wid] = M;
    }
    __syncthreads();
    const float M = fmaxf(wm2[0], wm2[1]);
    float e = 0.f;
    if (tid < CPB) {
        e = __expf(m - M);
        float se = s * e;
        #pragma unroll
        for (int o = 16; o; o >>= 1) se += __shfl_xor_sync(0xffffffffu, se, o);
        if (lane == 0) ws2[wid] = se;
    }
    __syncthreads();
    if (tid < CPB) alpha[tid] = e / (ws2[0] + ws2[1]);
    __syncthreads();

    // context: e = tid
    {
        float a = 0.f;
        const float* P = g_P + (size_t)b * CPB * E_ + tid;
        #pragma unroll 8
        for (int c = 0; c < CPB; ++c)
            a = fmaf(P[(size_t)c * E_], alpha[c], a);
        ctx[(size_t)b * E_ + tid] = a;
    }
    // weights rescale
    {
        float* w = weights + (size_t)b * T_;
        #pragma unroll
        for (int i = tid; i < T_; i += 512)
            w[i] *= alpha[i >> 6];
    }
}

// ---------------------------------------------------------------------------
extern "C" void kernel_launch(void* const* d_in, const int* in_sizes, int n_in,
                              void* d_out, int out_size) {
    const float* X     = (const float*)d_in[0];
    const float* dec   = (const float*)d_in[1];
    const float* W_enc = (const float*)d_in[2];
    const float* b_enc = (const float*)d_in[3];
    const float* W_dec = (const float*)d_in[4];
    const float* v_att = (const float*)d_in[5];
    const float* b_att = (const float*)d_in[6];

    float* ctx     = (float*)d_out;
    float* weights = (float*)d_out + B_ * E_;

    cudaFuncSetAttribute(scores_mma_kernel,
                         cudaFuncAttributeMaxDynamicSharedMemorySize, SMEM_TOTAL);

    convert_w_kernel<<<E_, A_>>>(W_enc);
    dproj_kernel<<<B_, A_>>>(dec, W_dec, b_enc);

    dim3 g1(T_ / 64, B_);
    scores_mma_kernel<<<g1, 256, SMEM_TOTAL>>>(X, v_att, b_att, weights);

    combine_kernel<<<B_, 512>>>(ctx, weights);
}

// round 11
// speedup vs baseline: 2.5080x; 1.0277x over previous
#include <cuda_runtime.h>
#include <cuda_fp16.h>
#include <cstdint>

#define B_  64
#define T_  4096
#define E_  512
#define A_  256
#define CPB 64                     // CTAs per batch (T/64)

// ---------------------------------------------------------------------------
// scratch (allocation-free)
// ---------------------------------------------------------------------------
__device__ float g_dproj[B_ * A_];
__device__ float g_P[(size_t)B_ * CPB * E_];       // partial contexts, 8MB
__device__ float g_m[B_ * CPB];                    // per-CTA local max
__device__ float g_s[B_ * CPB];                    // per-CTA local expsum
__device__ __align__(128) __half g_Wf[A_ * E_];    // [n][k] K-major fp16

// ---------------------------------------------------------------------------
// helpers
// ---------------------------------------------------------------------------
__device__ __forceinline__ uint32_t smem_u32(const void* p) {
    uint32_t a;
    asm("{ .reg .u64 t; cvta.to.shared.u64 t, %1; cvt.u32.u64 %0, t; }" : "=r"(a) : "l"(p));
    return a;
}
__device__ __forceinline__ uint32_t swz128(uint32_t o) { return o ^ ((o >> 3) & 0x70); }

#define CP_ASYNC16(dst, src) \
    asm volatile("cp.async.cg.shared.global [%0], [%1], 16;" :: "r"(dst), "l"(src) : "memory")
#define CP_COMMIT()  asm volatile("cp.async.commit_group;" ::: "memory")
#define CP_WAIT1()   asm volatile("cp.async.wait_group 1;" ::: "memory")
#define CP_WAIT0()   asm volatile("cp.async.wait_group 0;" ::: "memory")

#define LDM4(r, a) \
    asm volatile("ldmatrix.sync.aligned.m8n8.x4.shared.b16 {%0,%1,%2,%3}, [%4];" \
        : "=r"((r)[0]), "=r"((r)[1]), "=r"((r)[2]), "=r"((r)[3]) : "r"(a))

__device__ __forceinline__ void mma_fp16(float* c, const uint32_t* a, const uint32_t* b) {
    asm volatile(
        "mma.sync.aligned.m16n8k16.row.col.f32.f16.f16.f32 "
        "{%0,%1,%2,%3}, {%4,%5,%6,%7}, {%8,%9}, {%0,%1,%2,%3};"
        : "+f"(c[0]), "+f"(c[1]), "+f"(c[2]), "+f"(c[3])
        : "r"(a[0]), "r"(a[1]), "r"(a[2]), "r"(a[3]), "r"(b[0]), "r"(b[1]));
}

// ---------------------------------------------------------------------------
// small prep kernels
// ---------------------------------------------------------------------------
__global__ void convert_w_kernel(const float* __restrict__ W, int k0) {
    int k = k0 + blockIdx.x;    // 256 blocks per launch
    int n = threadIdx.x;        // 256
    g_Wf[n * E_ + k] = __float2half_rn(W[k * A_ + n]);
}

__global__ void dproj_kernel(const float* __restrict__ dec,
                             const float* __restrict__ Wd,
                             const float* __restrict__ b_enc) {
    int b = blockIdx.x;
    int a = threadIdx.x;
    const float* d = dec + b * E_;
    float s = b_enc[a];
    #pragma unroll 8
    for (int e = 0; e < E_; ++e)
        s = fmaf(d[e], Wd[e * A_ + a], s);
    g_dproj[b * A_ + a] = s;
}

// ---------------------------------------------------------------------------
// K1: fused fp16 HMMA scores GEMM + local softmax + partial context.
// CTA: M=64 x N=256, K=512 in 8 chunks of 64. 8 warps (2M x 4N), warp 32x64.
// X path: LDG fp32 (4 x float4/thread = full 64x64 tile!) -> regs -> cvt ->
// STS into double-buffered XH. W: cp.async dbl-buffered, refilled post-barrier.
// One __syncthreads per chunk. 2 CTAs/SM.
// ---------------------------------------------------------------------------
#define KC       64
#define NCH      8
#define OFF_XH   0                      // 2 x 8KB fp16 X tiles
#define OFF_W    16384                  // 2 x 32KB fp16 W
#define OFF_V    81920
#define OFF_DP   82944
#define OFF_RED  83968                  // 64 x 4 floats
#define OFF_U    85120                  // 64 floats
#define OFF_RW   85376                  // reduce scratch
#define SMEM_TOTAL 85504

__global__ void __launch_bounds__(256, 2)
scores_mma_kernel(const float* __restrict__ X,
                  const float* __restrict__ v_att,
                  const float* __restrict__ b_att,
                  float* __restrict__ weights)
{
    extern __shared__ char smem[];
    const uint32_t sb = smem_u32(smem);
    const int tid = threadIdx.x;
    const int lane = tid & 31, wid = tid >> 5;
    const int wm = wid >> 2, wn = wid & 3;      // 2 x 4 warp grid
    const int b = blockIdx.y;
    const int t0 = blockIdx.x * 64;
    const int cta = b * CPB + blockIdx.x;

    float* vs   = (float*)(smem + OFF_V);
    float* dps  = (float*)(smem + OFF_DP);
    float* red  = (float*)(smem + OFF_RED);
    float* usm  = (float*)(smem + OFF_U);
    float* rmax = (float*)(smem + OFF_RW);       // [8]
    float* rsum = rmax + 8;                      // [8]
    float* rsc  = rsum + 8;                      // [1]
    vs[tid]  = v_att[tid];
    dps[tid] = g_dproj[b * A_ + tid];

    const float* xrow = X + ((size_t)b * T_ + t0) * E_;

    float acc[2][8][4];
    #pragma unroll
    for (int mt = 0; mt < 2; ++mt)
        #pragma unroll
        for (int nt = 0; nt < 8; ++nt)
            #pragma unroll
            for (int e = 0; e < 4; ++e) acc[mt][nt][e] = 0.f;

    // per-lane ldmatrix base offsets (128B rows)
    const int rsel = lane & 15, chalf = lane >> 4;
    uint32_t abase[2], bbase[4];
    #pragma unroll
    for (int mt = 0; mt < 2; ++mt)
        abase[mt] = (uint32_t)(((wm << 5) + (mt << 4) + rsel) << 7) + (chalf << 4);
    #pragma unroll
    for (int n2 = 0; n2 < 4; ++n2)
        bbase[n2] = (uint32_t)(((wn << 6) + (n2 << 4) + rsel) << 7) + (chalf << 4);

    // X chunk: 64 rows x 64 fp32 = 1024 float4; thread handles 4 (it*256+tid)
    uint32_t xsts[4];
    int xr[4], xq[4];
    #pragma unroll
    for (int it = 0; it < 4; ++it) {
        int f = tid + (it << 8);
        xr[it] = f >> 4;                 // row 0..63
        xq[it] = f & 15;                 // float4 index in row
        xsts[it] = swz128((uint32_t)((xr[it] << 7) + (xq[it] << 3)));
    }

    auto ldg_x = [&](int c, float4* v) {
        const int kc = c * KC;
        #pragma unroll
        for (int it = 0; it < 4; ++it)
            v[it] = *(const float4*)(xrow + (size_t)xr[it] * E_ + kc + (xq[it] << 2));
    };
    auto sts_x = [&](int c, const float4* v) {
        const uint32_t bufo = (uint32_t)(c & 1) << 13;   // 8KB
        #pragma unroll
        for (int it = 0; it < 4; ++it) {
            uint32_t p0 = (uint32_t)__half_as_ushort(__float2half_rn(v[it].x)) |
                          ((uint32_t)__half_as_ushort(__float2half_rn(v[it].y)) << 16);
            uint32_t p1 = (uint32_t)__half_as_ushort(__float2half_rn(v[it].z)) |
                          ((uint32_t)__half_as_ushort(__float2half_rn(v[it].w)) << 16);
            *(uint2*)(smem + OFF_XH + bufo + xsts[it]) = make_uint2(p0, p1);
        }
    };
    auto load_w = [&](int c) {                           // W: 2048 x 16B, SW128
        const int kc = c * KC;
        const uint32_t s15 = (uint32_t)(c & 1) << 15;
        #pragma unroll
        for (int it = 0; it < 8; ++it) {
            int i = tid + (it << 8);
            int r = i >> 3, q = i & 7;
            const __half* src = g_Wf + (size_t)r * E_ + kc + (q << 3);
            uint32_t dst = sb + OFF_W + s15 + swz128((r << 7) + (q << 4));
            CP_ASYNC16(dst, src);
        }
        CP_COMMIT();
    };

    // prologue: W(0), W(1) async; XH(0) stored; X(1) prefetched to regs
    float4 nx[4];
    {
        float4 v[4];
        load_w(0);
        ldg_x(0, v);
        load_w(1);
        sts_x(0, v);
    }
    ldg_x(1, nx);
    __syncthreads();                                     // XH(0) visible

    for (int c = 0; c < NCH; ++c) {
        if (c + 1 < NCH) { CP_WAIT1(); }                 // W(c) done, W(c+1) in flight
        else             { CP_WAIT0(); }

        const uint32_t xh = sb + OFF_XH + ((uint32_t)(c & 1) << 13);
        const uint32_t wb = sb + OFF_W + ((uint32_t)(c & 1) << 15);

        // store XH(c+1) from prefetched regs (other buffer — safe during MMA(c))
        if (c + 1 < NCH) sts_x(c + 1, nx);
        // prefetch X(c+2) into regs (no smem hazard)
        if (c + 2 < NCH) ldg_x(c + 2, nx);

        #pragma unroll
        for (int ks = 0; ks < 4; ++ks) {
            const uint32_t koff = ks << 5;
            uint32_t A[2][4], Bf[4][4];
            #pragma unroll
            for (int mt = 0; mt < 2; ++mt) LDM4(A[mt], xh + swz128(abase[mt] + koff));
            #pragma unroll
            for (int n2 = 0; n2 < 4; ++n2) LDM4(Bf[n2], wb + swz128(bbase[n2] + koff));
            #pragma unroll
            for (int n2 = 0; n2 < 4; ++n2) {
                uint32_t be[2] = { Bf[n2][0], Bf[n2][2] };
                uint32_t bo[2] = { Bf[n2][1], Bf[n2][3] };
                #pragma unroll
                for (int mt = 0; mt < 2; ++mt) {
                    mma_fp16(acc[mt][n2 * 2],     A[mt], be);
                    mma_fp16(acc[mt][n2 * 2 + 1], A[mt], bo);
                }
            }
        }
        __syncthreads();     // reads of Wbuf(c&1)/XH(c) done; XH(c+1) visible

        // safe to refill W buffer (c&1) with chunk c+2 now
        if (c + 2 < NCH) load_w(c + 2);
    }

    // ---- epilogue: tanh + v dot, reduce to per-row score ----
    const int g = lane >> 2, t = lane & 3;
    #pragma unroll
    for (int mt = 0; mt < 2; ++mt) {
        float pa = 0.f, pb = 0.f;
        #pragma unroll
        for (int nt = 0; nt < 8; ++nt) {
            int col = (wn << 6) + (nt << 3) + (t << 1);
            float v0 = vs[col], v1 = vs[col + 1];
            float d0 = dps[col], d1 = dps[col + 1];
            pa = fmaf(v0, tanhf(acc[mt][nt][0] + d0), pa);
            pa = fmaf(v1, tanhf(acc[mt][nt][1] + d1), pa);
            pb = fmaf(v0, tanhf(acc[mt][nt][2] + d0), pb);
            pb = fmaf(v1, tanhf(acc[mt][nt][3] + d1), pb);
        }
        pa += __shfl_xor_sync(0xffffffffu, pa, 1);
        pa += __shfl_xor_sync(0xffffffffu, pa, 2);
        pb += __shfl_xor_sync(0xffffffffu, pb, 1);
        pb += __shfl_xor_sync(0xffffffffu, pb, 2);
        if (t == 0) {
            int row = (wm << 5) + (mt << 4) + g;
            red[row * 4 + wn]       = pa;
            red[(row + 8) * 4 + wn] = pb;
        }
    }
    __syncthreads();

    // ---- local softmax over 64 rows ----
    float sval = -1e30f;
    if (tid < 64)
        sval = red[tid * 4] + red[tid * 4 + 1] + red[tid * 4 + 2] + red[tid * 4 + 3]
             + b_att[0];
    float wmx = sval;
    #pragma unroll
    for (int o = 16; o; o >>= 1) wmx = fmaxf(wmx, __shfl_xor_sync(0xffffffffu, wmx, o));
    if (lane == 0 && wid < 2) rmax[wid] = wmx;
    __syncthreads();
    if (tid == 0) rsc[0] = fmaxf(rmax[0], rmax[1]);
    __syncthreads();
    const float m_c = rsc[0];

    float u = (tid < 64) ? __expf(sval - m_c) : 0.f;
    if (tid < 64) {
        usm[tid] = u;
        weights[(size_t)b * T_ + t0 + tid] = u;    // unnormalized; fixed in combine
    }
    float wsum = u;
    #pragma unroll
    for (int o = 16; o; o >>= 1) wsum += __shfl_xor_sync(0xffffffffu, wsum, o);
    if (lane == 0 && wid < 2) rsum[wid] = wsum;
    __syncthreads();
    if (tid == 0) {
        g_m[cta] = m_c;
        g_s[cta] = rsum[0] + rsum[1];
    }
    __syncthreads();

    // ---- partial context: P_c[e] = sum_t u_t * X[t, e] ----
    #pragma unroll
    for (int half = 0; half < 2; ++half) {
        const float* xp = xrow + tid + (half << 8);
        float a0 = 0.f, a1 = 0.f, a2 = 0.f, a3 = 0.f;
        #pragma unroll 4
        for (int tt = 0; tt < 64; tt += 4) {
            a0 = fmaf(usm[tt + 0], xp[(size_t)(tt + 0) * E_], a0);
            a1 = fmaf(usm[tt + 1], xp[(size_t)(tt + 1) * E_], a1);
            a2 = fmaf(usm[tt + 2], xp[(size_t)(tt + 2) * E_], a2);
            a3 = fmaf(usm[tt + 3], xp[(size_t)(tt + 3) * E_], a3);
        }
        g_P[(size_t)cta * E_ + tid + (half << 8)] = (a0 + a1) + (a2 + a3);
    }
}

// ---------------------------------------------------------------------------
// K2: combine — cross-CTA softmax algebra, context, weight rescale.
// ---------------------------------------------------------------------------
__global__ void combine_kernel(float* __restrict__ ctx,
                               float* __restrict__ weights)
{
    const int b = blockIdx.x;
    const int tid = threadIdx.x;
    const int lane = tid & 31, wid = tid >> 5;
    __shared__ float alpha[CPB];
    __shared__ float wm2[2], ws2[2];

    float m = -1e30f, s = 0.f;
    if (tid < CPB) {
        m = g_m[b * CPB + tid];
        s = g_s[b * CPB + tid];
    }
    if (tid < CPB) {
        float M = m;
        #pragma unroll
        for (int o = 16; o; o >>= 1) M = fmaxf(M, __shfl_xor_sync(0xffffffffu, M, o));
        if (lane == 0) wm2[wid] = M;
    }
    __syncthreads();
    const float M = fmaxf(wm2[0], wm2[1]);
    float e = 0.f;
    if (tid < CPB) {
        e = __expf(m - M);
        float se = s * e;
        #pragma unroll
        for (int o = 16; o; o >>= 1) se += __shfl_xor_sync(0xffffffffu, se, o);
        if (lane == 0) ws2[wid] = se;
    }
    __syncthreads();
    if (tid < CPB) alpha[tid] = e / (ws2[0] + ws2[1]);
    __syncthreads();

    // context: e = tid
    {
        float a = 0.f;
        const float* P = g_P + (size_t)b * CPB * E_ + tid;
        #pragma unroll 8
        for (int c = 0; c < CPB; ++c)
            a = fmaf(P[(size_t)c * E_], alpha[c], a);
        ctx[(size_t)b * E_ + tid] = a;
    }
    // weights rescale
    {
        float* w = weights + (size_t)b * T_;
        #pragma unroll
        for (int i = tid; i < T_; i += 512)
            w[i] *= alpha[i >> 6];
    }
}

// ---------------------------------------------------------------------------
extern "C" void kernel_launch(void* const* d_in, const int* in_sizes, int n_in,
                              void* d_out, int out_size) {
    const float* X     = (const float*)d_in[0];
    const float* dec   = (const float*)d_in[1];
    const float* W_enc = (const float*)d_in[2];
    const float* b_enc = (const float*)d_in[3];
    const float* W_dec = (const float*)d_in[4];
    const float* v_att = (const float*)d_in[5];
    const float* b_att = (const float*)d_in[6];

    float* ctx     = (float*)d_out;
    float* weights = (float*)d_out + B_ * E_;

    cudaFuncSetAttribute(scores_mma_kernel,
                         cudaFuncAttributeMaxDynamicSharedMemorySize, SMEM_TOTAL);

    convert_w_kernel<<<256, 256>>>(W_enc, 0);     // launch 1
    convert_w_kernel<<<256, 256>>>(W_enc, 256);   // launch 2
    dproj_kernel<<<B_, A_>>>(dec, W_dec, b_enc);  // launch 3

    dim3 g1(T_ / 64, B_);
    scores_mma_kernel<<<g1, 256, SMEM_TOTAL>>>(X, v_att, b_att, weights);  // launch 4

    combine_kernel<<<B_, 512>>>(ctx, weights);
}

// round 12
// speedup vs baseline: 2.5351x; 1.0108x over previous
#include <cuda_runtime.h>
#include <cuda_fp16.h>
#include <cstdint>

#define B_  64
#define T_  4096
#define E_  512
#define A_  256
#define CPB 64                     // CTAs per batch (T/64)

// ---------------------------------------------------------------------------
// scratch (allocation-free)
// ---------------------------------------------------------------------------
__device__ float g_dproj[B_ * A_];
__device__ float g_P[(size_t)B_ * CPB * E_];       // partial contexts, 8MB
__device__ float g_m[B_ * CPB];                    // per-CTA local max
__device__ float g_s[B_ * CPB];                    // per-CTA local expsum
__device__ __align__(128) __half g_Wf[A_ * E_];    // [n][k] K-major fp16

// ---------------------------------------------------------------------------
// helpers
// ---------------------------------------------------------------------------
__device__ __forceinline__ uint32_t smem_u32(const void* p) {
    uint32_t a;
    asm("{ .reg .u64 t; cvta.to.shared.u64 t, %1; cvt.u32.u64 %0, t; }" : "=r"(a) : "l"(p));
    return a;
}
__device__ __forceinline__ uint32_t swz128(uint32_t o) { return o ^ ((o >> 3) & 0x70); }

#define CP_ASYNC16(dst, src) \
    asm volatile("cp.async.cg.shared.global [%0], [%1], 16;" :: "r"(dst), "l"(src) : "memory")
#define CP_COMMIT()  asm volatile("cp.async.commit_group;" ::: "memory")
#define CP_WAIT1()   asm volatile("cp.async.wait_group 1;" ::: "memory")
#define CP_WAIT0()   asm volatile("cp.async.wait_group 0;" ::: "memory")

#define LDM4(r, a) \
    asm volatile("ldmatrix.sync.aligned.m8n8.x4.shared.b16 {%0,%1,%2,%3}, [%4];" \
        : "=r"((r)[0]), "=r"((r)[1]), "=r"((r)[2]), "=r"((r)[3]) : "r"(a))

// d = {lo=cvt(b), hi=cvt(a)}
#define CVT_F16X2(d, hi, lo) \
    asm("cvt.rn.f16x2.f32 %0, %1, %2;" : "=r"(d) : "f"(hi), "f"(lo))

__device__ __forceinline__ void mma_fp16(float* c, const uint32_t* a, const uint32_t* b) {
    asm volatile(
        "mma.sync.aligned.m16n8k16.row.col.f32.f16.f16.f32 "
        "{%0,%1,%2,%3}, {%4,%5,%6,%7}, {%8,%9}, {%0,%1,%2,%3};"
        : "+f"(c[0]), "+f"(c[1]), "+f"(c[2]), "+f"(c[3])
        : "r"(a[0]), "r"(a[1]), "r"(a[2]), "r"(a[3]), "r"(b[0]), "r"(b[1]));
}

// ---------------------------------------------------------------------------
// small prep kernels
// ---------------------------------------------------------------------------
__global__ void convert_w_kernel(const float* __restrict__ W, int k0) {
    int k = k0 + blockIdx.x;    // 256 blocks per launch
    int n = threadIdx.x;        // 256
    g_Wf[n * E_ + k] = __float2half_rn(W[k * A_ + n]);
}

__global__ void dproj_kernel(const float* __restrict__ dec,
                             const float* __restrict__ Wd,
                             const float* __restrict__ b_enc) {
    int b = blockIdx.x;
    int a = threadIdx.x;
    const float* d = dec + b * E_;
    float s = b_enc[a];
    #pragma unroll 8
    for (int e = 0; e < E_; ++e)
        s = fmaf(d[e], Wd[e * A_ + a], s);
    g_dproj[b * A_ + a] = s;
}

// ---------------------------------------------------------------------------
// K1: fused fp16 HMMA scores GEMM + local softmax + partial context.
// CTA: M=64 x N=256, K=512 in 8 chunks of 64. 8 warps (2M x 4N), warp 32x64.
// ALU-lean mainloop: hoisted swizzles (swz(base+koff)=swz(base)^koff),
// pointer-increment addressing, cvt.rn.f16x2 packing. 2 CTAs/SM.
// ---------------------------------------------------------------------------
#define KC       64
#define NCH      8
#define OFF_XH   0                      // 2 x 8KB fp16 X tiles
#define OFF_W    16384                  // 2 x 32KB fp16 W
#define OFF_V    81920
#define OFF_DP   82944
#define OFF_RED  83968                  // 64 x 4 floats
#define OFF_U    85120                  // 64 floats
#define OFF_RW   85376                  // reduce scratch
#define SMEM_TOTAL 85504

__global__ void __launch_bounds__(256, 2)
scores_mma_kernel(const float* __restrict__ X,
                  const float* __restrict__ v_att,
                  const float* __restrict__ b_att,
                  float* __restrict__ weights)
{
    extern __shared__ char smem[];
    const uint32_t sb = smem_u32(smem);
    const int tid = threadIdx.x;
    const int lane = tid & 31, wid = tid >> 5;
    const int wm = wid >> 2, wn = wid & 3;      // 2 x 4 warp grid
    const int b = blockIdx.y;
    const int t0 = blockIdx.x * 64;
    const int cta = b * CPB + blockIdx.x;

    float* vs   = (float*)(smem + OFF_V);
    float* dps  = (float*)(smem + OFF_DP);
    float* red  = (float*)(smem + OFF_RED);
    float* usm  = (float*)(smem + OFF_U);
    float* rmax = (float*)(smem + OFF_RW);       // [8]
    float* rsum = rmax + 8;                      // [8]
    float* rsc  = rsum + 8;                      // [1]
    vs[tid]  = v_att[tid];
    dps[tid] = g_dproj[b * A_ + tid];

    const float* xrow = X + ((size_t)b * T_ + t0) * E_;

    float acc[2][8][4];
    #pragma unroll
    for (int mt = 0; mt < 2; ++mt)
        #pragma unroll
        for (int nt = 0; nt < 8; ++nt)
            #pragma unroll
            for (int e = 0; e < 4; ++e) acc[mt][nt][e] = 0.f;

    // hoisted, pre-swizzled ldmatrix offsets (koff XORed in per use)
    const int rsel = lane & 15, chalf = lane >> 4;
    uint32_t aswz[2], bswz[4];
    #pragma unroll
    for (int mt = 0; mt < 2; ++mt)
        aswz[mt] = swz128((uint32_t)(((wm << 5) + (mt << 4) + rsel) << 7) + (chalf << 4));
    #pragma unroll
    for (int n2 = 0; n2 < 4; ++n2)
        bswz[n2] = swz128((uint32_t)(((wn << 6) + (n2 << 4) + rsel) << 7) + (chalf << 4));

    // X chunk: 64 rows x 64 fp32 = 1024 float4; thread handles 4 (it*256+tid)
    // Pointer-increment addressing: advance by KC floats per chunk.
    const float* xptr[4];
    uint32_t xsts[4];
    #pragma unroll
    for (int it = 0; it < 4; ++it) {
        int f = tid + (it << 8);
        int r = f >> 4, q = f & 15;
        xptr[it] = xrow + (size_t)r * E_ + (q << 2);
        xsts[it] = swz128((uint32_t)((r << 7) + (q << 3)));
    }
    // W cp.async: fixed dst swizzles + src offsets; src base advances by KC.
    const __half* wsrc = g_Wf;
    int woff[8];
    uint32_t wsts[8];
    #pragma unroll
    for (int it = 0; it < 8; ++it) {
        int i = tid + (it << 8);
        int r = i >> 3, q = i & 7;
        woff[it] = r * E_ + (q << 3);
        wsts[it] = sb + OFF_W + swz128((uint32_t)((r << 7) + (q << 4)));
    }

    auto ldg_x = [&](float4* v) {
        #pragma unroll
        for (int it = 0; it < 4; ++it) {
            v[it] = *(const float4*)xptr[it];
            xptr[it] += KC;
        }
    };
    auto sts_x = [&](int c, const float4* v) {
        const uint32_t bufo = (uint32_t)(c & 1) << 13;   // 8KB
        #pragma unroll
        for (int it = 0; it < 4; ++it) {
            uint32_t p0, p1;
            CVT_F16X2(p0, v[it].y, v[it].x);
            CVT_F16X2(p1, v[it].w, v[it].z);
            *(uint2*)(smem + OFF_XH + bufo + xsts[it]) = make_uint2(p0, p1);
        }
    };
    auto load_w = [&](int c) {                           // W: 2048 x 16B, SW128
        const uint32_t s15 = (uint32_t)(c & 1) << 15;
        #pragma unroll
        for (int it = 0; it < 8; ++it)
            CP_ASYNC16(wsts[it] + s15, wsrc + woff[it]);
        wsrc += KC;                                      // next chunk
        CP_COMMIT();
    };

    // prologue: W(0), W(1) async; XH(0) stored; X(1) prefetched to regs
    float4 nx[4];
    {
        float4 v[4];
        load_w(0);
        ldg_x(v);            // chunk 0
        load_w(1);
        sts_x(0, v);
    }
    ldg_x(nx);               // chunk 1
    __syncthreads();                                     // XH(0) visible

    for (int c = 0; c < NCH; ++c) {
        if (c + 1 < NCH) { CP_WAIT1(); }                 // W(c) done, W(c+1) in flight
        else             { CP_WAIT0(); }

        const uint32_t xh = sb + OFF_XH + ((uint32_t)(c & 1) << 13);
        const uint32_t wb = sb + OFF_W + ((uint32_t)(c & 1) << 15);

        // store XH(c+1) from prefetched regs (other buffer — safe during MMA(c))
        if (c + 1 < NCH) sts_x(c + 1, nx);
        // prefetch X(c+2) into regs (no smem hazard)
        if (c + 2 < NCH) ldg_x(nx);

        #pragma unroll
        for (int ks = 0; ks < 4; ++ks) {
            const uint32_t koff = ks << 5;
            uint32_t A[2][4], Bf[4][4];
            #pragma unroll
            for (int mt = 0; mt < 2; ++mt) LDM4(A[mt], xh + (aswz[mt] ^ koff));
            #pragma unroll
            for (int n2 = 0; n2 < 4; ++n2) LDM4(Bf[n2], wb + (bswz[n2] ^ koff));
            #pragma unroll
            for (int n2 = 0; n2 < 4; ++n2) {
                uint32_t be[2] = { Bf[n2][0], Bf[n2][2] };
                uint32_t bo[2] = { Bf[n2][1], Bf[n2][3] };
                #pragma unroll
                for (int mt = 0; mt < 2; ++mt) {
                    mma_fp16(acc[mt][n2 * 2],     A[mt], be);
                    mma_fp16(acc[mt][n2 * 2 + 1], A[mt], bo);
                }
            }
        }
        __syncthreads();     // reads of Wbuf(c&1)/XH(c) done; XH(c+1) visible

        // safe to refill W buffer (c&1) with chunk c+2 now
        if (c + 2 < NCH) load_w(c + 2);
    }

    // ---- epilogue: tanh + v dot, reduce to per-row score ----
    const int g = lane >> 2, t = lane & 3;
    #pragma unroll
    for (int mt = 0; mt < 2; ++mt) {
        float pa = 0.f, pb = 0.f;
        #pragma unroll
        for (int nt = 0; nt < 8; ++nt) {
            int col = (wn << 6) + (nt << 3) + (t << 1);
            float v0 = vs[col], v1 = vs[col + 1];
            float d0 = dps[col], d1 = dps[col + 1];
            pa = fmaf(v0, tanhf(acc[mt][nt][0] + d0), pa);
            pa = fmaf(v1, tanhf(acc[mt][nt][1] + d1), pa);
            pb = fmaf(v0, tanhf(acc[mt][nt][2] + d0), pb);
            pb = fmaf(v1, tanhf(acc[mt][nt][3] + d1), pb);
        }
        pa += __shfl_xor_sync(0xffffffffu, pa, 1);
        pa += __shfl_xor_sync(0xffffffffu, pa, 2);
        pb += __shfl_xor_sync(0xffffffffu, pb, 1);
        pb += __shfl_xor_sync(0xffffffffu, pb, 2);
        if (t == 0) {
            int row = (wm << 5) + (mt << 4) + g;
            red[row * 4 + wn]       = pa;
            red[(row + 8) * 4 + wn] = pb;
        }
    }
    __syncthreads();

    // ---- local softmax over 64 rows ----
    float sval = -1e30f;
    if (tid < 64)
        sval = red[tid * 4] + red[tid * 4 + 1] + red[tid * 4 + 2] + red[tid * 4 + 3]
             + b_att[0];
    float wmx = sval;
    #pragma unroll
    for (int o = 16; o; o >>= 1) wmx = fmaxf(wmx, __shfl_xor_sync(0xffffffffu, wmx, o));
    if (lane == 0 && wid < 2) rmax[wid] = wmx;
    __syncthreads();
    if (tid == 0) rsc[0] = fmaxf(rmax[0], rmax[1]);
    __syncthreads();
    const float m_c = rsc[0];

    float u = (tid < 64) ? __expf(sval - m_c) : 0.f;
    if (tid < 64) {
        usm[tid] = u;
        weights[(size_t)b * T_ + t0 + tid] = u;    // unnormalized; fixed in combine
    }
    float wsum = u;
    #pragma unroll
    for (int o = 16; o; o >>= 1) wsum += __shfl_xor_sync(0xffffffffu, wsum, o);
    if (lane == 0 && wid < 2) rsum[wid] = wsum;
    __syncthreads();
    if (tid == 0) {
        g_m[cta] = m_c;
        g_s[cta] = rsum[0] + rsum[1];
    }
    __syncthreads();

    // ---- partial context: P_c[e] = sum_t u_t * X[t, e] ----
    #pragma unroll
    for (int half = 0; half < 2; ++half) {
        const float* xp = xrow + tid + (half << 8);
        float a0 = 0.f, a1 = 0.f, a2 = 0.f, a3 = 0.f;
        #pragma unroll 4
        for (int tt = 0; tt < 64; tt += 4) {
            a0 = fmaf(usm[tt + 0], xp[(size_t)(tt + 0) * E_], a0);
            a1 = fmaf(usm[tt + 1], xp[(size_t)(tt + 1) * E_], a1);
            a2 = fmaf(usm[tt + 2], xp[(size_t)(tt + 2) * E_], a2);
            a3 = fmaf(usm[tt + 3], xp[(size_t)(tt + 3) * E_], a3);
        }
        g_P[(size_t)cta * E_ + tid + (half << 8)] = (a0 + a1) + (a2 + a3);
    }
}

// ---------------------------------------------------------------------------
// K2: combine — cross-CTA softmax algebra, context, weight rescale.
// ---------------------------------------------------------------------------
__global__ void combine_kernel(float* __restrict__ ctx,
                               float* __restrict__ weights)
{
    const int b = blockIdx.x;
    const int tid = threadIdx.x;
    const int lane = tid & 31, wid = tid >> 5;
    __shared__ float alpha[CPB];
    __shared__ float wm2[2], ws2[2];

    float m = -1e30f, s = 0.f;
    if (tid < CPB) {
        m = g_m[b * CPB + tid];
        s = g_s[b * CPB + tid];
    }
    if (tid < CPB) {
        float M = m;
        #pragma unroll
        for (int o = 16; o; o >>= 1) M = fmaxf(M, __shfl_xor_sync(0xffffffffu, M, o));
        if (lane == 0) wm2[wid] = M;
    }
    __syncthreads();
    const float M = fmaxf(wm2[0], wm2[1]);
    float e = 0.f;
    if (tid < CPB) {
        e = __expf(m - M);
        float se = s * e;
        #pragma unroll
        for (int o = 16; o; o >>= 1) se += __shfl_xor_sync(0xffffffffu, se, o);
        if (lane == 0) ws2[wid] = se;
    }
    __syncthreads();
    if (tid < CPB) alpha[tid] = e / (ws2[0] + ws2[1]);
    __syncthreads();

    // context: e = tid
    {
        float a = 0.f;
        const float* P = g_P + (size_t)b * CPB * E_ + tid;
        #pragma unroll 8
        for (int c = 0; c < CPB; ++c)
            a = fmaf(P[(size_t)c * E_], alpha[c], a);
        ctx[(size_t)b * E_ + tid] = a;
    }
    // weights rescale
    {
        float* w = weights + (size_t)b * T_;
        #pragma unroll
        for (int i = tid; i < T_; i += 512)
            w[i] *= alpha[i >> 6];
    }
}

// ---------------------------------------------------------------------------
extern "C" void kernel_launch(void* const* d_in, const int* in_sizes, int n_in,
                              void* d_out, int out_size) {
    const float* X     = (const float*)d_in[0];
    const float* dec   = (const float*)d_in[1];
    const float* W_enc = (const float*)d_in[2];
    const float* b_enc = (const float*)d_in[3];
    const float* W_dec = (const float*)d_in[4];
    const float* v_att = (const float*)d_in[5];
    const float* b_att = (const float*)d_in[6];

    float* ctx     = (float*)d_out;
    float* weights = (float*)d_out + B_ * E_;

    cudaFuncSetAttribute(scores_mma_kernel,
                         cudaFuncAttributeMaxDynamicSharedMemorySize, SMEM_TOTAL);

    convert_w_kernel<<<256, 256>>>(W_enc, 0);     // launch 1
    convert_w_kernel<<<256, 256>>>(W_enc, 256);   // launch 2
    dproj_kernel<<<B_, A_>>>(dec, W_dec, b_enc);  // launch 3

    dim3 g1(T_ / 64, B_);
    scores_mma_kernel<<<g1, 256, SMEM_TOTAL>>>(X, v_att, b_att, weights);  // launch 4

    combine_kernel<<<B_, 512>>>(ctx, weights);
}

// round 13
// speedup vs baseline: 2.7685x; 1.0921x over previous
#include <cuda_runtime.h>
#include <cuda_fp16.h>
#include <cstdint>

#define B_  64
#define T_  4096
#define E_  512
#define A_  256
#define CPB 64                     // CTAs per batch (T/64)

// ---------------------------------------------------------------------------
// scratch (allocation-free)
// ---------------------------------------------------------------------------
__device__ float g_dproj[B_ * A_];
__device__ float g_P[(size_t)B_ * CPB * E_];       // partial contexts, 8MB
__device__ float g_m[B_ * CPB];                    // per-CTA local max
__device__ float g_s[B_ * CPB];                    // per-CTA local expsum
__device__ __align__(128) __half g_Wf[A_ * E_];    // [n][k] K-major fp16

// ---------------------------------------------------------------------------
// helpers
// ---------------------------------------------------------------------------
__device__ __forceinline__ uint32_t smem_u32(const void* p) {
    uint32_t a;
    asm("{ .reg .u64 t; cvta.to.shared.u64 t, %1; cvt.u32.u64 %0, t; }" : "=r"(a) : "l"(p));
    return a;
}
__device__ __forceinline__ uint32_t swz128(uint32_t o) { return o ^ ((o >> 3) & 0x70); }

// hardware tanh (MUFU.TANH, sm_75+): 1 instruction vs ~dozens for tanhf
__device__ __forceinline__ float tanh_hw(float x) {
    float y;
    asm("tanh.approx.f32 %0, %1;" : "=f"(y) : "f"(x));
    return y;
}

#define CP_ASYNC16(dst, src) \
    asm volatile("cp.async.cg.shared.global [%0], [%1], 16;" :: "r"(dst), "l"(src) : "memory")
#define CP_COMMIT()  asm volatile("cp.async.commit_group;" ::: "memory")
#define CP_WAIT1()   asm volatile("cp.async.wait_group 1;" ::: "memory")
#define CP_WAIT0()   asm volatile("cp.async.wait_group 0;" ::: "memory")

#define LDM4(r, a) \
    asm volatile("ldmatrix.sync.aligned.m8n8.x4.shared.b16 {%0,%1,%2,%3}, [%4];" \
        : "=r"((r)[0]), "=r"((r)[1]), "=r"((r)[2]), "=r"((r)[3]) : "r"(a))

// d = {lo=cvt(lo), hi=cvt(hi)}
#define CVT_F16X2(d, hi, lo) \
    asm("cvt.rn.f16x2.f32 %0, %1, %2;" : "=r"(d) : "f"(hi), "f"(lo))

__device__ __forceinline__ void mma_fp16(float* c, const uint32_t* a, const uint32_t* b) {
    asm volatile(
        "mma.sync.aligned.m16n8k16.row.col.f32.f16.f16.f32 "
        "{%0,%1,%2,%3}, {%4,%5,%6,%7}, {%8,%9}, {%0,%1,%2,%3};"
        : "+f"(c[0]), "+f"(c[1]), "+f"(c[2]), "+f"(c[3])
        : "r"(a[0]), "r"(a[1]), "r"(a[2]), "r"(a[3]), "r"(b[0]), "r"(b[1]));
}

// ---------------------------------------------------------------------------
// small prep kernels
// ---------------------------------------------------------------------------
__global__ void convert_w_kernel(const float* __restrict__ W, int k0) {
    int k = k0 + blockIdx.x;    // 256 blocks per launch
    int n = threadIdx.x;        // 256
    g_Wf[n * E_ + k] = __float2half_rn(W[k * A_ + n]);
}

__global__ void dproj_kernel(const float* __restrict__ dec,
                             const float* __restrict__ Wd,
                             const float* __restrict__ b_enc) {
    int b = blockIdx.x;
    int a = threadIdx.x;
    const float* d = dec + b * E_;
    float s = b_enc[a];
    #pragma unroll 8
    for (int e = 0; e < E_; ++e)
        s = fmaf(d[e], Wd[e * A_ + a], s);
    g_dproj[b * A_ + a] = s;
}

// ---------------------------------------------------------------------------
// K1: fused fp16 HMMA scores GEMM + local softmax + partial context.
// CTA: M=64 x N=256, K=512 in 8 chunks of 64. 8 warps (2M x 4N), warp 32x64.
// Epilogue tanh via MUFU.TANH (tanh.approx) — accurate tanhf expanded to a
// huge ALU sequence that serialized after the GEMM (R12: alu pipe 39%).
// ---------------------------------------------------------------------------
#define KC       64
#define NCH      8
#define OFF_XH   0                      // 2 x 8KB fp16 X tiles
#define OFF_W    16384                  // 2 x 32KB fp16 W
#define OFF_V    81920
#define OFF_DP   82944
#define OFF_RED  83968                  // 64 x 4 floats
#define OFF_U    85120                  // 64 floats
#define OFF_RW   85376                  // reduce scratch
#define SMEM_TOTAL 85504

__global__ void __launch_bounds__(256, 2)
scores_mma_kernel(const float* __restrict__ X,
                  const float* __restrict__ v_att,
                  const float* __restrict__ b_att,
                  float* __restrict__ weights)
{
    extern __shared__ char smem[];
    const uint32_t sb = smem_u32(smem);
    const int tid = threadIdx.x;
    const int lane = tid & 31, wid = tid >> 5;
    const int wm = wid >> 2, wn = wid & 3;      // 2 x 4 warp grid
    const int b = blockIdx.y;
    const int t0 = blockIdx.x * 64;
    const int cta = b * CPB + blockIdx.x;

    float* vs   = (float*)(smem + OFF_V);
    float* dps  = (float*)(smem + OFF_DP);
    float* red  = (float*)(smem + OFF_RED);
    float* usm  = (float*)(smem + OFF_U);
    float* rmax = (float*)(smem + OFF_RW);       // [8]
    float* rsum = rmax + 8;                      // [8]
    float* rsc  = rsum + 8;                      // [1]
    vs[tid]  = v_att[tid];
    dps[tid] = g_dproj[b * A_ + tid];

    const float* xrow = X + ((size_t)b * T_ + t0) * E_;

    float acc[2][8][4];
    #pragma unroll
    for (int mt = 0; mt < 2; ++mt)
        #pragma unroll
        for (int nt = 0; nt < 8; ++nt)
            #pragma unroll
            for (int e = 0; e < 4; ++e) acc[mt][nt][e] = 0.f;

    // hoisted, pre-swizzled ldmatrix offsets (koff XORed in per use)
    const int rsel = lane & 15, chalf = lane >> 4;
    uint32_t aswz[2], bswz[4];
    #pragma unroll
    for (int mt = 0; mt < 2; ++mt)
        aswz[mt] = swz128((uint32_t)(((wm << 5) + (mt << 4) + rsel) << 7) + (chalf << 4));
    #pragma unroll
    for (int n2 = 0; n2 < 4; ++n2)
        bswz[n2] = swz128((uint32_t)(((wn << 6) + (n2 << 4) + rsel) << 7) + (chalf << 4));

    // X chunk: 64 rows x 64 fp32 = 1024 float4; thread handles 4 (it*256+tid)
    const float* xptr[4];
    uint32_t xsts[4];
    #pragma unroll
    for (int it = 0; it < 4; ++it) {
        int f = tid + (it << 8);
        int r = f >> 4, q = f & 15;
        xptr[it] = xrow + (size_t)r * E_ + (q << 2);
        xsts[it] = swz128((uint32_t)((r << 7) + (q << 3)));
    }
    // W cp.async: fixed dst swizzles + src offsets; src base advances by KC.
    const __half* wsrc = g_Wf;
    int woff[8];
    uint32_t wsts[8];
    #pragma unroll
    for (int it = 0; it < 8; ++it) {
        int i = tid + (it << 8);
        int r = i >> 3, q = i & 7;
        woff[it] = r * E_ + (q << 3);
        wsts[it] = sb + OFF_W + swz128((uint32_t)((r << 7) + (q << 4)));
    }

    auto ldg_x = [&](float4* v) {
        #pragma unroll
        for (int it = 0; it < 4; ++it) {
            v[it] = *(const float4*)xptr[it];
            xptr[it] += KC;
        }
    };
    auto sts_x = [&](int c, const float4* v) {
        const uint32_t bufo = (uint32_t)(c & 1) << 13;   // 8KB
        #pragma unroll
        for (int it = 0; it < 4; ++it) {
            uint32_t p0, p1;
            CVT_F16X2(p0, v[it].y, v[it].x);
            CVT_F16X2(p1, v[it].w, v[it].z);
            *(uint2*)(smem + OFF_XH + bufo + xsts[it]) = make_uint2(p0, p1);
        }
    };
    auto load_w = [&](int c) {                           // W: 2048 x 16B, SW128
        const uint32_t s15 = (uint32_t)(c & 1) << 15;
        #pragma unroll
        for (int it = 0; it < 8; ++it)
            CP_ASYNC16(wsts[it] + s15, wsrc + woff[it]);
        wsrc += KC;                                      // next chunk
        CP_COMMIT();
    };

    // prologue: W(0), W(1) async; XH(0) stored; X(1) prefetched to regs
    float4 nx[4];
    {
        float4 v[4];
        load_w(0);
        ldg_x(v);            // chunk 0
        load_w(1);
        sts_x(0, v);
    }
    ldg_x(nx);               // chunk 1
    __syncthreads();                                     // XH(0) visible

    for (int c = 0; c < NCH; ++c) {
        if (c + 1 < NCH) { CP_WAIT1(); }                 // W(c) done, W(c+1) in flight
        else             { CP_WAIT0(); }

        const uint32_t xh = sb + OFF_XH + ((uint32_t)(c & 1) << 13);
        const uint32_t wb = sb + OFF_W + ((uint32_t)(c & 1) << 15);

        // store XH(c+1) from prefetched regs (other buffer — safe during MMA(c))
        if (c + 1 < NCH) sts_x(c + 1, nx);
        // prefetch X(c+2) into regs (no smem hazard)
        if (c + 2 < NCH) ldg_x(nx);

        #pragma unroll
        for (int ks = 0; ks < 4; ++ks) {
            const uint32_t koff = ks << 5;
            uint32_t A[2][4], Bf[4][4];
            #pragma unroll
            for (int mt = 0; mt < 2; ++mt) LDM4(A[mt], xh + (aswz[mt] ^ koff));
            #pragma unroll
            for (int n2 = 0; n2 < 4; ++n2) LDM4(Bf[n2], wb + (bswz[n2] ^ koff));
            #pragma unroll
            for (int n2 = 0; n2 < 4; ++n2) {
                uint32_t be[2] = { Bf[n2][0], Bf[n2][2] };
                uint32_t bo[2] = { Bf[n2][1], Bf[n2][3] };
                #pragma unroll
                for (int mt = 0; mt < 2; ++mt) {
                    mma_fp16(acc[mt][n2 * 2],     A[mt], be);
                    mma_fp16(acc[mt][n2 * 2 + 1], A[mt], bo);
                }
            }
        }
        __syncthreads();     // reads of Wbuf(c&1)/XH(c) done; XH(c+1) visible

        // safe to refill W buffer (c&1) with chunk c+2 now
        if (c + 2 < NCH) load_w(c + 2);
    }

    // ---- epilogue: tanh (MUFU) + v dot, reduce to per-row score ----
    const int g = lane >> 2, t = lane & 3;
    #pragma unroll
    for (int mt = 0; mt < 2; ++mt) {
        float pa = 0.f, pb = 0.f;
        #pragma unroll
        for (int nt = 0; nt < 8; ++nt) {
            int col = (wn << 6) + (nt << 3) + (t << 1);
            float v0 = vs[col], v1 = vs[col + 1];
            float d0 = dps[col], d1 = dps[col + 1];
            pa = fmaf(v0, tanh_hw(acc[mt][nt][0] + d0), pa);
            pa = fmaf(v1, tanh_hw(acc[mt][nt][1] + d1), pa);
            pb = fmaf(v0, tanh_hw(acc[mt][nt][2] + d0), pb);
            pb = fmaf(v1, tanh_hw(acc[mt][nt][3] + d1), pb);
        }
        pa += __shfl_xor_sync(0xffffffffu, pa, 1);
        pa += __shfl_xor_sync(0xffffffffu, pa, 2);
        pb += __shfl_xor_sync(0xffffffffu, pb, 1);
        pb += __shfl_xor_sync(0xffffffffu, pb, 2);
        if (t == 0) {
            int row = (wm << 5) + (mt << 4) + g;
            red[row * 4 + wn]       = pa;
            red[(row + 8) * 4 + wn] = pb;
        }
    }
    __syncthreads();

    // ---- local softmax over 64 rows ----
    float sval = -1e30f;
    if (tid < 64)
        sval = red[tid * 4] + red[tid * 4 + 1] + red[tid * 4 + 2] + red[tid * 4 + 3]
             + b_att[0];
    float wmx = sval;
    #pragma unroll
    for (int o = 16; o; o >>= 1) wmx = fmaxf(wmx, __shfl_xor_sync(0xffffffffu, wmx, o));
    if (lane == 0 && wid < 2) rmax[wid] = wmx;
    __syncthreads();
    if (tid == 0) rsc[0] = fmaxf(rmax[0], rmax[1]);
    __syncthreads();
    const float m_c = rsc[0];

    float u = (tid < 64) ? __expf(sval - m_c) : 0.f;
    if (tid < 64) {
        usm[tid] = u;
        weights[(size_t)b * T_ + t0 + tid] = u;    // unnormalized; fixed in combine
    }
    float wsum = u;
    #pragma unroll
    for (int o = 16; o; o >>= 1) wsum += __shfl_xor_sync(0xffffffffu, wsum, o);
    if (lane == 0 && wid < 2) rsum[wid] = wsum;
    __syncthreads();
    if (tid == 0) {
        g_m[cta] = m_c;
        g_s[cta] = rsum[0] + rsum[1];
    }
    __syncthreads();

    // ---- partial context: P_c[e] = sum_t u_t * X[t, e] ----
    #pragma unroll
    for (int half = 0; half < 2; ++half) {
        const float* xp = xrow + tid + (half << 8);
        float a0 = 0.f, a1 = 0.f, a2 = 0.f, a3 = 0.f;
        #pragma unroll 4
        for (int tt = 0; tt < 64; tt += 4) {
            a0 = fmaf(usm[tt + 0], xp[(size_t)(tt + 0) * E_], a0);
            a1 = fmaf(usm[tt + 1], xp[(size_t)(tt + 1) * E_], a1);
            a2 = fmaf(usm[tt + 2], xp[(size_t)(tt + 2) * E_], a2);
            a3 = fmaf(usm[tt + 3], xp[(size_t)(tt + 3) * E_], a3);
        }
        g_P[(size_t)cta * E_ + tid + (half << 8)] = (a0 + a1) + (a2 + a3);
    }
}

// ---------------------------------------------------------------------------
// K2: combine — cross-CTA softmax algebra, context, weight rescale.
// ---------------------------------------------------------------------------
__global__ void combine_kernel(float* __restrict__ ctx,
                               float* __restrict__ weights)
{
    const int b = blockIdx.x;
    const int tid = threadIdx.x;
    const int lane = tid & 31, wid = tid >> 5;
    __shared__ float alpha[CPB];
    __shared__ float wm2[2], ws2[2];

    float m = -1e30f, s = 0.f;
    if (tid < CPB) {
        m = g_m[b * CPB + tid];
        s = g_s[b * CPB + tid];
    }
    if (tid < CPB) {
        float M = m;
        #pragma unroll
        for (int o = 16; o; o >>= 1) M = fmaxf(M, __shfl_xor_sync(0xffffffffu, M, o));
        if (lane == 0) wm2[wid] = M;
    }
    __syncthreads();
    const float M = fmaxf(wm2[0], wm2[1]);
    float e = 0.f;
    if (tid < CPB) {
        e = __expf(m - M);
        float se = s * e;
        #pragma unroll
        for (int o = 16; o; o >>= 1) se += __shfl_xor_sync(0xffffffffu, se, o);
        if (lane == 0) ws2[wid] = se;
    }
    __syncthreads();
    if (tid < CPB) alpha[tid] = e / (ws2[0] + ws2[1]);
    __syncthreads();

    // context: e = tid
    {
        float a = 0.f;
        const float* P = g_P + (size_t)b * CPB * E_ + tid;
        #pragma unroll 8
        for (int c = 0; c < CPB; ++c)
            a = fmaf(P[(size_t)c * E_], alpha[c], a);
        ctx[(size_t)b * E_ + tid] = a;
    }
    // weights rescale
    {
        float* w = weights + (size_t)b * T_;
        #pragma unroll
        for (int i = tid; i < T_; i += 512)
            w[i] *= alpha[i >> 6];
    }
}

// ---------------------------------------------------------------------------
extern "C" void kernel_launch(void* const* d_in, const int* in_sizes, int n_in,
                              void* d_out, int out_size) {
    const float* X     = (const float*)d_in[0];
    const float* dec   = (const float*)d_in[1];
    const float* W_enc = (const float*)d_in[2];
    const float* b_enc = (const float*)d_in[3];
    const float* W_dec = (const float*)d_in[4];
    const float* v_att = (const float*)d_in[5];
    const float* b_att = (const float*)d_in[6];

    float* ctx     = (float*)d_out;
    float* weights = (float*)d_out + B_ * E_;

    cudaFuncSetAttribute(scores_mma_kernel,
                         cudaFuncAttributeMaxDynamicSharedMemorySize, SMEM_TOTAL);

    convert_w_kernel<<<256, 256>>>(W_enc, 0);     // launch 1
    convert_w_kernel<<<256, 256>>>(W_enc, 256);   // launch 2
    dproj_kernel<<<B_, A_>>>(dec, W_dec, b_enc);  // launch 3

    dim3 g1(T_ / 64, B_);
    scores_mma_kernel<<<g1, 256, SMEM_TOTAL>>>(X, v_att, b_att, weights);  // launch 4

    combine_kernel<<<B_, 512>>>(ctx, weights);
}